// round 11
// baseline (speedup 1.0000x reference)
#include <cuda_runtime.h>
#include <cuda_bf16.h>
#include <cstdint>
#include <cstddef>

#define BATCH 4
#define SEQ   4096
#define DIM   512
#define MTOT  (BATCH * SEQ)             // 16384
#define PLX   ((size_t)MTOT * DIM)      // x2 plane stride
#define PLW   ((size_t)(3 * DIM) * DIM) // Wcat2 plane stride (rows: Wk|Wq|Wv)
#define PLK   ((size_t)SEQ * DIM)       // K2/Q2c per-batch plane stride
#define PLP   ((size_t)SEQ * SEQ)       // P2 per-batch plane stride
#define PLV   ((size_t)DIM * SEQ)       // Vt2 per-batch plane stride

// ------------------------- scratch (device globals) -------------------------
__device__ __align__(128) __nv_bfloat16 g_x2 [2 * PLX];
__device__ __align__(128) __nv_bfloat16 g_Wc2[2 * PLW];
__device__ __align__(128) __nv_bfloat16 g_K2 [BATCH * 2 * PLK];
__device__ __align__(128) __nv_bfloat16 g_Q2c[BATCH * 2 * PLK];
__device__ __align__(128) __nv_bfloat16 g_Vt2[BATCH * 2 * PLV];
__device__ __align__(128) __nv_bfloat16 g_P2 [(size_t)BATCH * 2 * PLP];
__device__ __align__(128) float         g_rs [MTOT];
__device__ __align__(128) int           g_sel [MTOT];   // j -> t (within batch), 0-padded
__device__ __align__(128) int           g_nc  [BATCH];
__device__ __align__(128) int           g_ncp [BATCH];

// ------------------------------ PTX helpers --------------------------------
__device__ __forceinline__ uint32_t smem_u32(const void* p) {
    uint32_t a;
    asm("{ .reg .u64 t; cvta.to.shared.u64 t, %1; cvt.u32.u64 %0, t; }" : "=r"(a) : "l"(p));
    return a;
}
__device__ __forceinline__ void cp16(uint32_t s, const void* g) {
    asm volatile("cp.async.cg.shared.global [%0], [%1], 16;" :: "r"(s), "l"(g));
}
__device__ __forceinline__ void cp_commit() {
    asm volatile("cp.async.commit_group;" ::: "memory");
}
template <int N>
__device__ __forceinline__ void cp_wait() {
    asm volatile("cp.async.wait_group %0;" :: "n"(N) : "memory");
}
__device__ __forceinline__ void mma16816(float* d, const uint32_t* a, const uint32_t* b) {
    asm volatile(
        "mma.sync.aligned.m16n8k16.row.col.f32.bf16.bf16.f32 "
        "{%0,%1,%2,%3}, {%4,%5,%6,%7}, {%8,%9}, {%0,%1,%2,%3};"
        : "+f"(d[0]), "+f"(d[1]), "+f"(d[2]), "+f"(d[3])
        : "r"(a[0]), "r"(a[1]), "r"(a[2]), "r"(a[3]), "r"(b[0]), "r"(b[1]));
}
__device__ __forceinline__ void ldsm4(uint32_t* r, uint32_t addr) {
    asm volatile("ldmatrix.sync.aligned.m8n8.x4.shared.b16 {%0,%1,%2,%3}, [%4];"
                 : "=r"(r[0]), "=r"(r[1]), "=r"(r[2]), "=r"(r[3]) : "r"(addr));
}
__device__ __forceinline__ void stcs32(void* p, uint32_t v) {
    asm volatile("st.global.cs.u32 [%0], %1;" :: "l"(p), "r"(v) : "memory");
}
__device__ __forceinline__ void stcs64f(void* p, float v0, float v1) {
    asm volatile("st.global.cs.v2.f32 [%0], {%1, %2};" :: "l"(p), "f"(v0), "f"(v1) : "memory");
}
__device__ __forceinline__ uint32_t swz(int row, int chunk) {
    return (uint32_t)(row * 64 + (((chunk) ^ ((row >> 1) & 3)) << 4));
}

#define BM 128
#define BN 128
#define BKC 32
#define STAGES 3
#define TILE 8192
#define STAGE_BYTES (4 * TILE)
#define GSMEM (STAGES * STAGE_BYTES)   // 98304

// Mainloop core. Requires locals: tid, sbase, wm, wn, lane, NC, acc,
// aP0, aP1, bP0, bP1 (row pointers incl. +c0*8), Ap, Bp, so0, so1.
#define GEMM_CORE()                                                            \
    const int arow_l = wm * 64 + ((lane >> 3) & 1) * 8 + (lane & 7);           \
    const int akb    = lane >> 4;                                              \
    const int asw    = (arow_l >> 1) & 3;                                      \
    const uint32_t abase = (uint32_t)(arow_l * 64);                            \
    const int brow_l = wn * 32 + ((lane >> 4) & 1) * 8 + (lane & 7);           \
    const int bkb    = (lane >> 3) & 1;                                        \
    const int bsw    = (brow_l >> 1) & 3;                                      \
    const uint32_t bbase = (uint32_t)(brow_l * 64);                            \
    auto load_stage = [&](int s, int kb) {                                     \
        const uint32_t st = sbase + s * STAGE_BYTES;                           \
        const int ko = kb * BKC;                                               \
        cp16(st + so0,            aP0 + ko);                                   \
        cp16(st + TILE + so0,     aP0 + Ap + ko);                              \
        cp16(st + 2 * TILE + so0, bP0 + ko);                                   \
        cp16(st + 3 * TILE + so0, bP0 + Bp + ko);                              \
        cp16(st + so1,            aP1 + ko);                                   \
        cp16(st + TILE + so1,     aP1 + Ap + ko);                              \
        cp16(st + 2 * TILE + so1, bP1 + ko);                                   \
        cp16(st + 3 * TILE + so1, bP1 + Bp + ko);                              \
    };                                                                         \
    _Pragma("unroll")                                                          \
    for (int s = 0; s < STAGES - 1; s++) { load_stage(s, s); cp_commit(); }    \
    for (int i = 0; i < NC; i++) {                                             \
        const int pf = i + STAGES - 1;                                         \
        if (pf < NC) load_stage(pf % STAGES, pf);                              \
        cp_commit();                                                           \
        cp_wait<STAGES - 1>();                                                 \
        __syncthreads();                                                       \
        const uint32_t st  = sbase + (i % STAGES) * STAGE_BYTES;               \
        const uint32_t sAh = st;                                               \
        const uint32_t sAl = st + TILE;                                        \
        const uint32_t sBh = st + 2 * TILE;                                    \
        const uint32_t sBl = st + 3 * TILE;                                    \
        _Pragma("unroll")                                                      \
        for (int k16 = 0; k16 < 2; k16++) {                                    \
            const uint32_t axo = (uint32_t)(((2 * k16 + akb) ^ asw) << 4);     \
            const uint32_t bxo = (uint32_t)(((2 * k16 + bkb) ^ bsw) << 4);     \
            uint32_t af[4][4], bh[4][2], bl[4][2];                             \
            _Pragma("unroll")                                                  \
            for (int mt = 0; mt < 4; mt++)                                     \
                ldsm4(af[mt], sAh + abase + mt * 1024 + axo);                  \
            _Pragma("unroll")                                                  \
            for (int ntp = 0; ntp < 2; ntp++) {                                \
                uint32_t t4[4];                                                \
                ldsm4(t4, sBh + bbase + ntp * 1024 + bxo);                     \
                bh[ntp * 2 + 0][0] = t4[0]; bh[ntp * 2 + 0][1] = t4[1];        \
                bh[ntp * 2 + 1][0] = t4[2]; bh[ntp * 2 + 1][1] = t4[3];        \
            }                                                                  \
            _Pragma("unroll")                                                  \
            for (int ntp = 0; ntp < 2; ntp++) {                                \
                uint32_t t4[4];                                                \
                ldsm4(t4, sBl + bbase + ntp * 1024 + bxo);                     \
                bl[ntp * 2 + 0][0] = t4[0]; bl[ntp * 2 + 0][1] = t4[1];        \
                bl[ntp * 2 + 1][0] = t4[2]; bl[ntp * 2 + 1][1] = t4[3];        \
            }                                                                  \
            _Pragma("unroll")                                                  \
            for (int mt = 0; mt < 4; mt++)                                     \
                _Pragma("unroll")                                              \
                for (int nt = 0; nt < 4; nt++)                                 \
                    mma16816(acc[mt][nt], af[mt], bh[nt]);                     \
            _Pragma("unroll")                                                  \
            for (int mt = 0; mt < 4; mt++)                                     \
                _Pragma("unroll")                                              \
                for (int nt = 0; nt < 4; nt++)                                 \
                    mma16816(acc[mt][nt], af[mt], bl[nt]);                     \
            _Pragma("unroll")                                                  \
            for (int mt = 0; mt < 4; mt++)                                     \
                ldsm4(af[mt], sAl + abase + mt * 1024 + axo);                  \
            _Pragma("unroll")                                                  \
            for (int mt = 0; mt < 4; mt++)                                     \
                _Pragma("unroll")                                              \
                for (int nt = 0; nt < 4; nt++)                                 \
                    mma16816(acc[mt][nt], af[mt], bh[nt]);                     \
        }                                                                      \
        __syncthreads();                                                       \
    }

#define DECL_ACC()                                                             \
    float acc[4][4][4];                                                        \
    _Pragma("unroll")                                                          \
    for (int mt = 0; mt < 4; mt++)                                             \
        _Pragma("unroll")                                                      \
        for (int nt = 0; nt < 4; nt++)                                         \
            _Pragma("unroll")                                                  \
            for (int j = 0; j < 4; j++) acc[mt][nt][j] = 0.0f;

#define SPLIT2(v0, v1, hp, lp)                                                 \
    __nv_bfloat16 h0 = __float2bfloat16(v0);                                   \
    __nv_bfloat16 h1 = __float2bfloat16(v1);                                   \
    __nv_bfloat16 l0 = __float2bfloat16((v0) - __bfloat162float(h0));          \
    __nv_bfloat16 l1 = __float2bfloat16((v1) - __bfloat162float(h1));          \
    __nv_bfloat162 hp; hp.x = h0; hp.y = h1;                                   \
    __nv_bfloat162 lp; lp.x = l0; lp.y = l1;

// ---------------------------------------------------------------------------
// QV projection, compacted rows (batch = blockIdx.z, A rows via sel gather).
// N = 1024: cols [0,512) -> Q2c rows j; cols [512,1024) -> Vt2 (transposed).
// grid (8, 32, 4) — y sized for worst-case ncp=4096.
// ---------------------------------------------------------------------------
__global__ void __launch_bounds__(256, 2)
gemm_qv(const __nv_bfloat16* __restrict__ x2, const __nv_bfloat16* __restrict__ Wc2,
        __nv_bfloat16* __restrict__ Q2c, __nv_bfloat16* __restrict__ Vt2,
        const int* __restrict__ sel, const int* __restrict__ ncv,
        const int* __restrict__ ncp)
{
    extern __shared__ __align__(128) char smem[];
    const uint32_t sbase = smem_u32(smem);
    const int tid = threadIdx.x;
    const int z   = blockIdx.z;
    const int bm  = blockIdx.y * BM;
    if (bm >= ncp[z]) return;
    const int nc  = ncv[z];
    const int bn  = blockIdx.x * BN;
    const int wid = tid >> 5, lane = tid & 31;
    const int wm = wid >> 2, wn = wid & 3;
    const int lr = lane >> 2, lc = lane & 3;

    const int r0 = tid >> 2, c0 = tid & 3;
    const uint32_t so0 = swz(r0, c0);
    const uint32_t so1 = swz(r0 + 64, c0);

    const int t0 = sel[z * SEQ + bm + r0];
    const int t1 = sel[z * SEQ + bm + r0 + 64];
    const __nv_bfloat16* aP0 = x2 + ((size_t)z * SEQ + t0) * DIM + c0 * 8;
    const __nv_bfloat16* aP1 = x2 + ((size_t)z * SEQ + t1) * DIM + c0 * 8;
    const __nv_bfloat16* Wqv = Wc2 + (size_t)512 * DIM;
    const __nv_bfloat16* bP0 = Wqv + (size_t)(bn + r0) * DIM + c0 * 8;
    const __nv_bfloat16* bP1 = Wqv + (size_t)(bn + r0 + 64) * DIM + c0 * 8;
    const size_t Ap = PLX, Bp = PLW;
    const int NC = DIM / BKC;   // 16

    DECL_ACC()
    GEMM_CORE()

    if (bn < 512) {
        // Q epilogue: rows already compacted (j), skip padding
        #pragma unroll
        for (int mt = 0; mt < 4; mt++) {
            #pragma unroll
            for (int half = 0; half < 2; half++) {
                const int j = bm + wm * 64 + mt * 16 + half * 8 + lr;
                if (j >= nc) continue;
                #pragma unroll
                for (int nt = 0; nt < 4; nt++) {
                    const int c = bn + wn * 32 + nt * 8 + lc * 2;
                    SPLIT2(acc[mt][nt][half * 2], acc[mt][nt][half * 2 + 1], hp, lp)
                    __nv_bfloat16* dst = Q2c + (size_t)z * 2 * PLK
                                        + (size_t)j * DIM + c;
                    *reinterpret_cast<__nv_bfloat162*>(dst)       = hp;
                    *reinterpret_cast<__nv_bfloat162*>(dst + PLK) = lp;
                }
            }
        }
    } else {
        // V epilogue: smem transpose -> split2 compacted Vt2
        float* sv = reinterpret_cast<float*>(smem);   // [128][129]
        #pragma unroll
        for (int mt = 0; mt < 4; mt++) {
            #pragma unroll
            for (int half = 0; half < 2; half++) {
                const int tok = wm * 64 + mt * 16 + half * 8 + lr;
                #pragma unroll
                for (int nt = 0; nt < 4; nt++) {
                    const int c = wn * 32 + nt * 8 + lc * 2;
                    sv[tok * 129 + c]     = acc[mt][nt][half * 2 + 0];
                    sv[tok * 129 + c + 1] = acc[mt][nt][half * 2 + 1];
                }
            }
        }
        __syncthreads();
        const int d0 = bn - 512;
        #pragma unroll
        for (int tg = 0; tg < 4; tg++) {
            const int tok = tg * 32 + lane;
            const int j   = bm + tok;
            if (j >= nc) continue;
            __nv_bfloat16* base = Vt2 + (size_t)z * 2 * PLV + j;
            #pragma unroll
            for (int dd = 0; dd < 16; dd++) {
                const int d = wid * 16 + dd;
                const float v = sv[tok * 129 + d];
                const __nv_bfloat16 h = __float2bfloat16(v);
                const __nv_bfloat16 l = __float2bfloat16(v - __bfloat162float(h));
                __nv_bfloat16* o = base + (size_t)(d0 + d) * SEQ;
                o[0]   = h;
                o[PLV] = l;
            }
        }
    }
}

// ---------------------------------------------------------------------------
// K projection: all 16384 tokens, N=512. grid (4, 128).
// ---------------------------------------------------------------------------
__global__ void __launch_bounds__(256, 2)
gemm_k(const __nv_bfloat16* __restrict__ x2, const __nv_bfloat16* __restrict__ Wc2,
       __nv_bfloat16* __restrict__ K2)
{
    extern __shared__ __align__(128) char smem[];
    const uint32_t sbase = smem_u32(smem);
    const int tid = threadIdx.x;
    const int bm  = blockIdx.y * BM;
    const int bn  = blockIdx.x * BN;
    const int wid = tid >> 5, lane = tid & 31;
    const int wm = wid >> 2, wn = wid & 3;
    const int lr = lane >> 2, lc = lane & 3;

    const int r0 = tid >> 2, c0 = tid & 3;
    const uint32_t so0 = swz(r0, c0);
    const uint32_t so1 = swz(r0 + 64, c0);

    const __nv_bfloat16* aP0 = x2 + (size_t)(bm + r0) * DIM + c0 * 8;
    const __nv_bfloat16* aP1 = x2 + (size_t)(bm + r0 + 64) * DIM + c0 * 8;
    const __nv_bfloat16* bP0 = Wc2 + (size_t)(bn + r0) * DIM + c0 * 8;
    const __nv_bfloat16* bP1 = Wc2 + (size_t)(bn + r0 + 64) * DIM + c0 * 8;
    const size_t Ap = PLX, Bp = PLW;
    const int NC = DIM / BKC;

    DECL_ACC()
    GEMM_CORE()

    #pragma unroll
    for (int mt = 0; mt < 4; mt++) {
        #pragma unroll
        for (int half = 0; half < 2; half++) {
            const int row = bm + wm * 64 + mt * 16 + half * 8 + lr;
            const int b = row >> 12;
            const int orow = row & 4095;
            #pragma unroll
            for (int nt = 0; nt < 4; nt++) {
                const int c = bn + wn * 32 + nt * 8 + lc * 2;
                SPLIT2(acc[mt][nt][half * 2], acc[mt][nt][half * 2 + 1], hp, lp)
                __nv_bfloat16* dst = K2 + (size_t)b * 2 * PLK
                                    + (size_t)orow * DIM + c;
                *reinterpret_cast<__nv_bfloat162*>(dst)       = hp;
                *reinterpret_cast<__nv_bfloat162*>(dst + PLK) = lp;
            }
        }
    }
}

// ---------------------------------------------------------------------------
// Scores: P2 = exp(scale * K2 @ Q2c^T) gated by col<nc, + rowsum atomics.
// P2 written with streaming stores (read much later by PV; keep L2 for operands).
// ---------------------------------------------------------------------------
__global__ void __launch_bounds__(256, 2)
gemm_s(const __nv_bfloat16* __restrict__ K2, const __nv_bfloat16* __restrict__ Q2c,
       __nv_bfloat16* __restrict__ P2, float* __restrict__ rsum,
       const int* __restrict__ ncv, const int* __restrict__ ncp, float alpha)
{
    extern __shared__ __align__(128) char smem[];
    const uint32_t sbase = smem_u32(smem);
    const int tid = threadIdx.x;
    const int z   = blockIdx.z;
    const int bn  = blockIdx.x * BN;
    const int bm  = blockIdx.y * BM;
    const int np  = ncp[z];
    if (bn >= np) return;
    const int nc  = ncv[z];
    const int wid = tid >> 5, lane = tid & 31;
    const int wm = wid >> 2, wn = wid & 3;
    const int lr = lane >> 2, lc = lane & 3;

    const int r0 = tid >> 2, c0 = tid & 3;
    const uint32_t so0 = swz(r0, c0);
    const uint32_t so1 = swz(r0 + 64, c0);

    const __nv_bfloat16* Ab = K2  + (size_t)z * 2 * PLK;
    const __nv_bfloat16* Bb = Q2c + (size_t)z * 2 * PLK;
    const __nv_bfloat16* aP0 = Ab + (size_t)(bm + r0) * DIM + c0 * 8;
    const __nv_bfloat16* aP1 = Ab + (size_t)(bm + r0 + 64) * DIM + c0 * 8;
    const __nv_bfloat16* bP0 = Bb + (size_t)(bn + r0) * DIM + c0 * 8;
    const __nv_bfloat16* bP1 = Bb + (size_t)(bn + r0 + 64) * DIM + c0 * 8;
    const size_t Ap = PLK, Bp = PLK;
    const int NC = DIM / BKC;

    DECL_ACC()
    GEMM_CORE()

    float* ssum = reinterpret_cast<float*>(smem);
    if (tid < 128) ssum[tid] = 0.0f;
    __syncthreads();
    #pragma unroll
    for (int mt = 0; mt < 4; mt++) {
        #pragma unroll
        for (int half = 0; half < 2; half++) {
            const int rl  = wm * 64 + mt * 16 + half * 8 + lr;
            const int row = bm + rl;
            float partial = 0.0f;
            #pragma unroll
            for (int nt = 0; nt < 4; nt++) {
                const int col = bn + wn * 32 + nt * 8 + lc * 2;
                float v0 = acc[mt][nt][half * 2 + 0];
                float v1 = acc[mt][nt][half * 2 + 1];
                v0 = (col     < nc) ? __expf(v0 * alpha) : 0.0f;
                v1 = (col + 1 < nc) ? __expf(v1 * alpha) : 0.0f;
                partial += v0 + v1;
                SPLIT2(v0, v1, hp, lp)
                __nv_bfloat16* dst = P2 + (size_t)z * 2 * PLP
                                    + (size_t)row * SEQ + col;
                stcs32(dst,       *reinterpret_cast<uint32_t*>(&hp));
                stcs32(dst + PLP, *reinterpret_cast<uint32_t*>(&lp));
            }
            atomicAdd(&ssum[rl], partial);
        }
    }
    __syncthreads();
    if (tid < 128) atomicAdd(rsum + z * SEQ + bm + tid, ssum[tid]);
}

// ---------------------------------------------------------------------------
// PV: out = (P2 @ Vt2) / rsum, per-batch K extent = ncp[z]. Streaming out.
// ---------------------------------------------------------------------------
__global__ void __launch_bounds__(256, 2)
gemm_pv(const __nv_bfloat16* __restrict__ P2, const __nv_bfloat16* __restrict__ Vt2,
        float* __restrict__ out, const float* __restrict__ rsum,
        const int* __restrict__ ncp)
{
    extern __shared__ __align__(128) char smem[];
    const uint32_t sbase = smem_u32(smem);
    const int tid = threadIdx.x;
    const int z   = blockIdx.z;
    const int bm  = blockIdx.y * BM;
    const int bn  = blockIdx.x * BN;
    const int wid = tid >> 5, lane = tid & 31;
    const int wm = wid >> 2, wn = wid & 3;
    const int lr = lane >> 2, lc = lane & 3;

    const int r0 = tid >> 2, c0 = tid & 3;
    const uint32_t so0 = swz(r0, c0);
    const uint32_t so1 = swz(r0 + 64, c0);

    const __nv_bfloat16* Ab = P2  + (size_t)z * 2 * PLP;
    const __nv_bfloat16* Bb = Vt2 + (size_t)z * 2 * PLV;
    const __nv_bfloat16* aP0 = Ab + (size_t)(bm + r0) * SEQ + c0 * 8;
    const __nv_bfloat16* aP1 = Ab + (size_t)(bm + r0 + 64) * SEQ + c0 * 8;
    const __nv_bfloat16* bP0 = Bb + (size_t)(bn + r0) * SEQ + c0 * 8;
    const __nv_bfloat16* bP1 = Bb + (size_t)(bn + r0 + 64) * SEQ + c0 * 8;
    const size_t Ap = PLP, Bp = PLV;
    const int NC = ncp[z] / BKC;

    DECL_ACC()
    GEMM_CORE()

    #pragma unroll
    for (int mt = 0; mt < 4; mt++) {
        #pragma unroll
        for (int half = 0; half < 2; half++) {
            const int row = bm + wm * 64 + mt * 16 + half * 8 + lr;
            const float inv = 1.0f / rsum[z * SEQ + row];
            #pragma unroll
            for (int nt = 0; nt < 4; nt++) {
                const int col = bn + wn * 32 + nt * 8 + lc * 2;
                stcs64f(out + (size_t)z * PLK + (size_t)row * DIM + col,
                        acc[mt][nt][half * 2 + 0] * inv,
                        acc[mt][nt][half * 2 + 1] * inv);
            }
        }
    }
}

// -------------------- mask prefix-scan (+sel build, +rs zero) ---------------
__global__ __launch_bounds__(1024)
void mask_scan_kernel(const int* __restrict__ mask, int* __restrict__ sel,
                      int* __restrict__ ncarr, int* __restrict__ ncpadarr,
                      float* __restrict__ rs)
{
    const int b   = blockIdx.x;
    const int tid = threadIdx.x;
    const int* m  = mask + b * SEQ;
    int v[4], s = 0;
    #pragma unroll
    for (int i = 0; i < 4; i++) {
        v[i] = m[tid * 4 + i];
        s += v[i];
        rs[b * SEQ + tid * 4 + i] = 0.0f;
        sel[b * SEQ + tid * 4 + i] = 0;        // padding default
    }
    const int lane = tid & 31, warp = tid >> 5;
    int sc = s;
    #pragma unroll
    for (int off = 1; off < 32; off <<= 1) {
        int t = __shfl_up_sync(0xffffffffu, sc, off);
        if (lane >= off) sc += t;
    }
    __shared__ int wsum[32];
    if (lane == 31) wsum[warp] = sc;
    __syncthreads();
    if (warp == 0) {
        int w = wsum[lane];
        #pragma unroll
        for (int off = 1; off < 32; off <<= 1) {
            int t = __shfl_up_sync(0xffffffffu, w, off);
            if (lane >= off) w += t;
        }
        wsum[lane] = w;
    }
    __syncthreads();
    int base = (warp > 0 ? wsum[warp - 1] : 0) + sc - s;   // exclusive prefix
    __syncthreads();                                       // zero-fill done
    #pragma unroll
    for (int i = 0; i < 4; i++) {
        if (v[i]) sel[b * SEQ + base] = tid * 4 + i;
        base += v[i];
    }
    if (tid == 1023) {
        ncarr[b]    = base;
        ncpadarr[b] = (base + 127) & ~127;
    }
}

// ------------ merged fp32->hi/lo split of x, Wk, Wq, Wv --------------------
#define NX (MTOT * DIM)       // 8388608
#define NWEL (DIM * DIM)      // 262144
__global__ void prep_kernel(const float* __restrict__ x,
                            const float* __restrict__ Wk,
                            const float* __restrict__ Wq,
                            const float* __restrict__ Wv,
                            __nv_bfloat16* __restrict__ x2,
                            __nv_bfloat16* __restrict__ wc2)
{
    const int i = blockIdx.x * 256 + threadIdx.x;
    float v;
    __nv_bfloat16* hi;
    if (i < NX) {
        v = x[i];
        hi = x2 + i;
        __nv_bfloat16 h = __float2bfloat16(v);
        hi[0]   = h;
        hi[PLX] = __float2bfloat16(v - __bfloat162float(h));
        return;
    }
    const int j = i - NX;
    if (j < NWEL)            { v = Wk[j];            hi = wc2 + j; }
    else if (j < 2 * NWEL)   { v = Wq[j - NWEL];     hi = wc2 + 512 * DIM + (j - NWEL); }
    else if (j < 3 * NWEL)   { v = Wv[j - 2 * NWEL]; hi = wc2 + 1024 * DIM + (j - 2 * NWEL); }
    else return;
    __nv_bfloat16 h = __float2bfloat16(v);
    hi[0]   = h;
    hi[PLW] = __float2bfloat16(v - __bfloat162float(h));
}

// zero Vt2 padding cols [nc, np) in both planes
__global__ void pad_vt_kernel(__nv_bfloat16* __restrict__ T2,
                              const int* __restrict__ ncarr,
                              const int* __restrict__ ncpadarr)
{
    const int b  = blockIdx.y;
    const int nc = ncarr[b], np = ncpadarr[b];
    const int pad = np - nc;
    if (pad == 0) return;
    const int total = pad * DIM;
    const __nv_bfloat16 zz = __float2bfloat16(0.0f);
    for (int i = blockIdx.x * blockDim.x + threadIdx.x; i < total;
         i += gridDim.x * blockDim.x) {
        const int d = i / pad;
        const int j = nc + (i - d * pad);
        __nv_bfloat16* o = T2 + (size_t)b * 2 * PLV + (size_t)d * SEQ + j;
        o[0]   = zz;
        o[PLV] = zz;
    }
}

// ---------------------------------------------------------------------------
extern "C" void kernel_launch(void* const* d_in, const int* in_sizes, int n_in,
                              void* d_out, int out_size)
{
    const float* x    = (const float*)d_in[0];
    const int*   mask = (const int*)  d_in[1];
    const float* Wk   = (const float*)d_in[2];
    const float* Wq   = (const float*)d_in[3];
    const float* Wv   = (const float*)d_in[4];
    float*       out  = (float*)d_out;

    __nv_bfloat16 *x2, *wc2, *k2, *q2c, *vt2, *p2;
    float *rs;
    int *sel, *ncv, *ncp;
    cudaGetSymbolAddress((void**)&x2,  g_x2);
    cudaGetSymbolAddress((void**)&wc2, g_Wc2);
    cudaGetSymbolAddress((void**)&k2,  g_K2);
    cudaGetSymbolAddress((void**)&q2c, g_Q2c);
    cudaGetSymbolAddress((void**)&vt2, g_Vt2);
    cudaGetSymbolAddress((void**)&p2,  g_P2);
    cudaGetSymbolAddress((void**)&rs,  g_rs);
    cudaGetSymbolAddress((void**)&sel, g_sel);
    cudaGetSymbolAddress((void**)&ncv, g_nc);
    cudaGetSymbolAddress((void**)&ncp, g_ncp);

    cudaFuncSetAttribute(gemm_qv, cudaFuncAttributeMaxDynamicSharedMemorySize, GSMEM);
    cudaFuncSetAttribute(gemm_k,  cudaFuncAttributeMaxDynamicSharedMemorySize, GSMEM);
    cudaFuncSetAttribute(gemm_s,  cudaFuncAttributeMaxDynamicSharedMemorySize, GSMEM);
    cudaFuncSetAttribute(gemm_pv, cudaFuncAttributeMaxDynamicSharedMemorySize, GSMEM);

    const float scale = 0.044194173824159216f;  // 1/sqrt(512)

    // 0) mask scan: sel + counts + rs zero
    mask_scan_kernel<<<BATCH, 1024>>>(mask, sel, ncv, ncp, rs);

    // 1) merged splits (x + [Wk;Wq;Wv])
    prep_kernel<<<(NX + 3 * NWEL + 255) / 256, 256>>>(x, Wk, Wq, Wv, x2, wc2);

    // 1b) zero Vt2 padding cols
    pad_vt_kernel<<<dim3(64, BATCH), 256>>>(vt2, ncv, ncp);

    // 2) projections
    gemm_k <<<dim3(4, 128),    256, GSMEM>>>(x2, wc2, k2);
    gemm_qv<<<dim3(8, 32, 4),  256, GSMEM>>>(x2, wc2, q2c, vt2, sel, ncv, ncp);

    // 3) scores + exp + rowsum
    gemm_s<<<dim3(32, 32, BATCH), 256, GSMEM>>>(k2, q2c, p2, rs, ncv, ncp, scale);

    // 4) out = (P2 @ Vt2) / rowsum
    gemm_pv<<<dim3(DIM / BN, SEQ / BM, BATCH), 256, GSMEM>>>(p2, vt2, out, rs, ncp);
}

// round 12
// speedup vs baseline: 1.0285x; 1.0285x over previous
#include <cuda_runtime.h>
#include <cuda_bf16.h>
#include <cstdint>
#include <cstddef>

#define BATCH 4
#define SEQ   4096
#define DIM   512
#define MTOT  (BATCH * SEQ)             // 16384
#define PLX   ((size_t)MTOT * DIM)      // x2 plane stride
#define PLW   ((size_t)(3 * DIM) * DIM) // Wcat2 plane stride (rows: Wk|Wq|Wv)
#define PLK   ((size_t)SEQ * DIM)       // K2/Q2c per-batch plane stride
#define PLP   ((size_t)SEQ * SEQ)       // P2 per-batch plane stride
#define PLV   ((size_t)DIM * SEQ)       // Vt2 per-batch plane stride

// ------------------------- scratch (device globals) -------------------------
__device__ __align__(128) __nv_bfloat16 g_x2 [2 * PLX];
__device__ __align__(128) __nv_bfloat16 g_Wc2[2 * PLW];
__device__ __align__(128) __nv_bfloat16 g_K2 [BATCH * 2 * PLK];
__device__ __align__(128) __nv_bfloat16 g_Q2c[BATCH * 2 * PLK];
__device__ __align__(128) __nv_bfloat16 g_Vt2[BATCH * 2 * PLV];
__device__ __align__(128) __nv_bfloat16 g_P2 [(size_t)BATCH * 2 * PLP];
__device__ __align__(128) float         g_rs [MTOT];
__device__ __align__(128) int           g_sel [MTOT];   // j -> t (within batch), 0-padded
__device__ __align__(128) int           g_nc  [BATCH];
__device__ __align__(128) int           g_ncp [BATCH];

// ------------------------------ PTX helpers --------------------------------
__device__ __forceinline__ uint32_t smem_u32(const void* p) {
    uint32_t a;
    asm("{ .reg .u64 t; cvta.to.shared.u64 t, %1; cvt.u32.u64 %0, t; }" : "=r"(a) : "l"(p));
    return a;
}
__device__ __forceinline__ void cp16(uint32_t s, const void* g) {
    asm volatile("cp.async.cg.shared.global [%0], [%1], 16;" :: "r"(s), "l"(g));
}
__device__ __forceinline__ void cp_commit() {
    asm volatile("cp.async.commit_group;" ::: "memory");
}
template <int N>
__device__ __forceinline__ void cp_wait() {
    asm volatile("cp.async.wait_group %0;" :: "n"(N) : "memory");
}
__device__ __forceinline__ void mma16816(float* d, const uint32_t* a, const uint32_t* b) {
    asm volatile(
        "mma.sync.aligned.m16n8k16.row.col.f32.bf16.bf16.f32 "
        "{%0,%1,%2,%3}, {%4,%5,%6,%7}, {%8,%9}, {%0,%1,%2,%3};"
        : "+f"(d[0]), "+f"(d[1]), "+f"(d[2]), "+f"(d[3])
        : "r"(a[0]), "r"(a[1]), "r"(a[2]), "r"(a[3]), "r"(b[0]), "r"(b[1]));
}
__device__ __forceinline__ void ldsm4(uint32_t* r, uint32_t addr) {
    asm volatile("ldmatrix.sync.aligned.m8n8.x4.shared.b16 {%0,%1,%2,%3}, [%4];"
                 : "=r"(r[0]), "=r"(r[1]), "=r"(r[2]), "=r"(r[3]) : "r"(addr));
}
__device__ __forceinline__ void stcs32(void* p, uint32_t v) {
    asm volatile("st.global.cs.u32 [%0], %1;" :: "l"(p), "r"(v) : "memory");
}
__device__ __forceinline__ void stcs64f(void* p, float v0, float v1) {
    asm volatile("st.global.cs.v2.f32 [%0], {%1, %2};" :: "l"(p), "f"(v0), "f"(v1) : "memory");
}
__device__ __forceinline__ uint32_t swz(int row, int chunk) {
    return (uint32_t)(row * 64 + (((chunk) ^ ((row >> 1) & 3)) << 4));
}

// ---- geometry: BM=64 x BN=128, BK=32, 3 stages, 3 CTAs/SM target ----------
#define BM 64
#define BN 128
#define BKC 32
#define STAGES 3
#define TILE_A 4096                    // 64 rows * 64 B
#define TILE_B 8192                    // 128 rows * 64 B
#define STAGE_BYTES (2 * TILE_A + 2 * TILE_B)   // 24576: Ah|Al|Bh|Bl
#define OFF_AL TILE_A
#define OFF_BH (2 * TILE_A)
#define OFF_BL (2 * TILE_A + TILE_B)
#define GSMEM (STAGES * STAGE_BYTES)   // 73728

// Mainloop core. Requires locals: tid, sbase, wm, wn, lane, NC, acc,
// aP0 (A row r0), bP0, bP1 (B rows r0, r0+64), Ap, Bp, soA, soB0, soB1.
#define GEMM_CORE()                                                            \
    const int arow_l = wm * 32 + ((lane >> 3) & 1) * 8 + (lane & 7);           \
    const int akb    = lane >> 4;                                              \
    const int asw    = (arow_l >> 1) & 3;                                      \
    const uint32_t abase = (uint32_t)(arow_l * 64);                            \
    const int brow_l = wn * 32 + ((lane >> 4) & 1) * 8 + (lane & 7);           \
    const int bkb    = (lane >> 3) & 1;                                        \
    const int bsw    = (brow_l >> 1) & 3;                                      \
    const uint32_t bbase = (uint32_t)(brow_l * 64);                            \
    auto load_stage = [&](int s, int kb) {                                     \
        const uint32_t st = sbase + s * STAGE_BYTES;                           \
        const int ko = kb * BKC;                                               \
        cp16(st + soA,           aP0 + ko);                                    \
        cp16(st + OFF_AL + soA,  aP0 + Ap + ko);                               \
        cp16(st + OFF_BH + soB0, bP0 + ko);                                    \
        cp16(st + OFF_BL + soB0, bP0 + Bp + ko);                               \
        cp16(st + OFF_BH + soB1, bP1 + ko);                                    \
        cp16(st + OFF_BL + soB1, bP1 + Bp + ko);                               \
    };                                                                         \
    _Pragma("unroll")                                                          \
    for (int s = 0; s < STAGES - 1; s++) { load_stage(s, s); cp_commit(); }    \
    for (int i = 0; i < NC; i++) {                                             \
        const int pf = i + STAGES - 1;                                         \
        if (pf < NC) load_stage(pf % STAGES, pf);                              \
        cp_commit();                                                           \
        cp_wait<STAGES - 1>();                                                 \
        __syncthreads();                                                       \
        const uint32_t st  = sbase + (i % STAGES) * STAGE_BYTES;               \
        const uint32_t sAh = st;                                               \
        const uint32_t sAl = st + OFF_AL;                                      \
        const uint32_t sBh = st + OFF_BH;                                      \
        const uint32_t sBl = st + OFF_BL;                                      \
        _Pragma("unroll")                                                      \
        for (int k16 = 0; k16 < 2; k16++) {                                    \
            const uint32_t axo = (uint32_t)(((2 * k16 + akb) ^ asw) << 4);     \
            const uint32_t bxo = (uint32_t)(((2 * k16 + bkb) ^ bsw) << 4);     \
            uint32_t af[2][4], bh[4][2], bl[4][2];                             \
            _Pragma("unroll")                                                  \
            for (int mt = 0; mt < 2; mt++)                                     \
                ldsm4(af[mt], sAh + abase + mt * 1024 + axo);                  \
            _Pragma("unroll")                                                  \
            for (int ntp = 0; ntp < 2; ntp++) {                                \
                uint32_t t4[4];                                                \
                ldsm4(t4, sBh + bbase + ntp * 1024 + bxo);                     \
                bh[ntp * 2 + 0][0] = t4[0]; bh[ntp * 2 + 0][1] = t4[1];        \
                bh[ntp * 2 + 1][0] = t4[2]; bh[ntp * 2 + 1][1] = t4[3];        \
            }                                                                  \
            _Pragma("unroll")                                                  \
            for (int ntp = 0; ntp < 2; ntp++) {                                \
                uint32_t t4[4];                                                \
                ldsm4(t4, sBl + bbase + ntp * 1024 + bxo);                     \
                bl[ntp * 2 + 0][0] = t4[0]; bl[ntp * 2 + 0][1] = t4[1];        \
                bl[ntp * 2 + 1][0] = t4[2]; bl[ntp * 2 + 1][1] = t4[3];        \
            }                                                                  \
            _Pragma("unroll")                                                  \
            for (int mt = 0; mt < 2; mt++)                                     \
                _Pragma("unroll")                                              \
                for (int nt = 0; nt < 4; nt++)                                 \
                    mma16816(acc[mt][nt], af[mt], bh[nt]);                     \
            _Pragma("unroll")                                                  \
            for (int mt = 0; mt < 2; mt++)                                     \
                _Pragma("unroll")                                              \
                for (int nt = 0; nt < 4; nt++)                                 \
                    mma16816(acc[mt][nt], af[mt], bl[nt]);                     \
            _Pragma("unroll")                                                  \
            for (int mt = 0; mt < 2; mt++)                                     \
                ldsm4(af[mt], sAl + abase + mt * 1024 + axo);                  \
            _Pragma("unroll")                                                  \
            for (int mt = 0; mt < 2; mt++)                                     \
                _Pragma("unroll")                                              \
                for (int nt = 0; nt < 4; nt++)                                 \
                    mma16816(acc[mt][nt], af[mt], bh[nt]);                     \
        }                                                                      \
        __syncthreads();                                                       \
    }

#define DECL_ACC()                                                             \
    float acc[2][4][4];                                                        \
    _Pragma("unroll")                                                          \
    for (int mt = 0; mt < 2; mt++)                                             \
        _Pragma("unroll")                                                      \
        for (int nt = 0; nt < 4; nt++)                                         \
            _Pragma("unroll")                                                  \
            for (int j = 0; j < 4; j++) acc[mt][nt][j] = 0.0f;

#define SPLIT2(v0, v1, hp, lp)                                                 \
    __nv_bfloat16 h0 = __float2bfloat16(v0);                                   \
    __nv_bfloat16 h1 = __float2bfloat16(v1);                                   \
    __nv_bfloat16 l0 = __float2bfloat16((v0) - __bfloat162float(h0));          \
    __nv_bfloat16 l1 = __float2bfloat16((v1) - __bfloat162float(h1));          \
    __nv_bfloat162 hp; hp.x = h0; hp.y = h1;                                   \
    __nv_bfloat162 lp; lp.x = l0; lp.y = l1;

// load-mapping locals shared by all kernels
#define LOAD_MAP()                                                             \
    const int r0 = tid >> 2, c0 = tid & 3;                                     \
    const uint32_t soA  = swz(r0, c0);                                         \
    const uint32_t soB0 = soA;                                                 \
    const uint32_t soB1 = swz(r0 + 64, c0);

// ---------------------------------------------------------------------------
// QV projection, compacted rows. grid (8, 64, 4).
// cols [0,512) -> Q2c rows j; [512,1024) -> Vt2 (transposed split).
// ---------------------------------------------------------------------------
__global__ void __launch_bounds__(256, 3)
gemm_qv(const __nv_bfloat16* __restrict__ x2, const __nv_bfloat16* __restrict__ Wc2,
        __nv_bfloat16* __restrict__ Q2c, __nv_bfloat16* __restrict__ Vt2,
        const int* __restrict__ sel, const int* __restrict__ ncv,
        const int* __restrict__ ncp)
{
    extern __shared__ __align__(128) char smem[];
    const uint32_t sbase = smem_u32(smem);
    const int tid = threadIdx.x;
    const int z   = blockIdx.z;
    const int bm  = blockIdx.y * BM;
    if (bm >= ncp[z]) return;
    const int nc  = ncv[z];
    const int bn  = blockIdx.x * BN;
    const int wid = tid >> 5, lane = tid & 31;
    const int wm = wid >> 2, wn = wid & 3;
    const int lr = lane >> 2, lc = lane & 3;

    LOAD_MAP()
    const int t0 = sel[z * SEQ + bm + r0];
    const __nv_bfloat16* aP0 = x2 + ((size_t)z * SEQ + t0) * DIM + c0 * 8;
    const __nv_bfloat16* Wqv = Wc2 + (size_t)512 * DIM;
    const __nv_bfloat16* bP0 = Wqv + (size_t)(bn + r0) * DIM + c0 * 8;
    const __nv_bfloat16* bP1 = Wqv + (size_t)(bn + r0 + 64) * DIM + c0 * 8;
    const size_t Ap = PLX, Bp = PLW;
    const int NC = DIM / BKC;   // 16

    DECL_ACC()
    GEMM_CORE()

    if (bn < 512) {
        #pragma unroll
        for (int mt = 0; mt < 2; mt++) {
            #pragma unroll
            for (int half = 0; half < 2; half++) {
                const int j = bm + wm * 32 + mt * 16 + half * 8 + lr;
                if (j >= nc) continue;
                #pragma unroll
                for (int nt = 0; nt < 4; nt++) {
                    const int c = bn + wn * 32 + nt * 8 + lc * 2;
                    SPLIT2(acc[mt][nt][half * 2], acc[mt][nt][half * 2 + 1], hp, lp)
                    __nv_bfloat16* dst = Q2c + (size_t)z * 2 * PLK
                                        + (size_t)j * DIM + c;
                    *reinterpret_cast<__nv_bfloat162*>(dst)       = hp;
                    *reinterpret_cast<__nv_bfloat162*>(dst + PLK) = lp;
                }
            }
        }
    } else {
        // V epilogue: smem transpose [64 tok][128 d] -> split2 Vt2
        float* sv = reinterpret_cast<float*>(smem);   // [64][129]
        #pragma unroll
        for (int mt = 0; mt < 2; mt++) {
            #pragma unroll
            for (int half = 0; half < 2; half++) {
                const int tok = wm * 32 + mt * 16 + half * 8 + lr;
                #pragma unroll
                for (int nt = 0; nt < 4; nt++) {
                    const int c = wn * 32 + nt * 8 + lc * 2;
                    sv[tok * 129 + c]     = acc[mt][nt][half * 2 + 0];
                    sv[tok * 129 + c + 1] = acc[mt][nt][half * 2 + 1];
                }
            }
        }
        __syncthreads();
        const int d0 = bn - 512;
        #pragma unroll
        for (int tg = 0; tg < 2; tg++) {
            const int tok = tg * 32 + lane;
            const int j   = bm + tok;
            if (j >= nc) continue;
            __nv_bfloat16* base = Vt2 + (size_t)z * 2 * PLV + j;
            #pragma unroll
            for (int dd = 0; dd < 16; dd++) {
                const int d = wid * 16 + dd;
                const float v = sv[tok * 129 + d];
                const __nv_bfloat16 h = __float2bfloat16(v);
                const __nv_bfloat16 l = __float2bfloat16(v - __bfloat162float(h));
                __nv_bfloat16* o = base + (size_t)(d0 + d) * SEQ;
                o[0]   = h;
                o[PLV] = l;
            }
        }
    }
}

// ---------------------------------------------------------------------------
// K projection: all 16384 tokens, N=512. grid (4, 256).
// ---------------------------------------------------------------------------
__global__ void __launch_bounds__(256, 3)
gemm_k(const __nv_bfloat16* __restrict__ x2, const __nv_bfloat16* __restrict__ Wc2,
       __nv_bfloat16* __restrict__ K2)
{
    extern __shared__ __align__(128) char smem[];
    const uint32_t sbase = smem_u32(smem);
    const int tid = threadIdx.x;
    const int bm  = blockIdx.y * BM;
    const int bn  = blockIdx.x * BN;
    const int wid = tid >> 5, lane = tid & 31;
    const int wm = wid >> 2, wn = wid & 3;
    const int lr = lane >> 2, lc = lane & 3;

    LOAD_MAP()
    const __nv_bfloat16* aP0 = x2 + (size_t)(bm + r0) * DIM + c0 * 8;
    const __nv_bfloat16* bP0 = Wc2 + (size_t)(bn + r0) * DIM + c0 * 8;
    const __nv_bfloat16* bP1 = Wc2 + (size_t)(bn + r0 + 64) * DIM + c0 * 8;
    const size_t Ap = PLX, Bp = PLW;
    const int NC = DIM / BKC;

    DECL_ACC()
    GEMM_CORE()

    #pragma unroll
    for (int mt = 0; mt < 2; mt++) {
        #pragma unroll
        for (int half = 0; half < 2; half++) {
            const int row = bm + wm * 32 + mt * 16 + half * 8 + lr;
            const int b = row >> 12;
            const int orow = row & 4095;
            #pragma unroll
            for (int nt = 0; nt < 4; nt++) {
                const int c = bn + wn * 32 + nt * 8 + lc * 2;
                SPLIT2(acc[mt][nt][half * 2], acc[mt][nt][half * 2 + 1], hp, lp)
                __nv_bfloat16* dst = K2 + (size_t)b * 2 * PLK
                                    + (size_t)orow * DIM + c;
                *reinterpret_cast<__nv_bfloat162*>(dst)       = hp;
                *reinterpret_cast<__nv_bfloat162*>(dst + PLK) = lp;
            }
        }
    }
}

// ---------------------------------------------------------------------------
// Scores: P2 = exp(scale * K2 @ Q2c^T) gated col<nc, rowsum atomics.
// grid (32, 64, 4); early exit bn>=ncp[z]. Streaming stores for P2.
// ---------------------------------------------------------------------------
__global__ void __launch_bounds__(256, 3)
gemm_s(const __nv_bfloat16* __restrict__ K2, const __nv_bfloat16* __restrict__ Q2c,
       __nv_bfloat16* __restrict__ P2, float* __restrict__ rsum,
       const int* __restrict__ ncv, const int* __restrict__ ncp, float alpha)
{
    extern __shared__ __align__(128) char smem[];
    const uint32_t sbase = smem_u32(smem);
    const int tid = threadIdx.x;
    const int z   = blockIdx.z;
    const int bn  = blockIdx.x * BN;
    const int bm  = blockIdx.y * BM;
    if (bn >= ncp[z]) return;
    const int nc  = ncv[z];
    const int wid = tid >> 5, lane = tid & 31;
    const int wm = wid >> 2, wn = wid & 3;
    const int lr = lane >> 2, lc = lane & 3;

    LOAD_MAP()
    const __nv_bfloat16* Ab = K2  + (size_t)z * 2 * PLK;
    const __nv_bfloat16* Bb = Q2c + (size_t)z * 2 * PLK;
    const __nv_bfloat16* aP0 = Ab + (size_t)(bm + r0) * DIM + c0 * 8;
    const __nv_bfloat16* bP0 = Bb + (size_t)(bn + r0) * DIM + c0 * 8;
    const __nv_bfloat16* bP1 = Bb + (size_t)(bn + r0 + 64) * DIM + c0 * 8;
    const size_t Ap = PLK, Bp = PLK;
    const int NC = DIM / BKC;

    DECL_ACC()
    GEMM_CORE()

    float* ssum = reinterpret_cast<float*>(smem);
    if (tid < 64) ssum[tid] = 0.0f;
    __syncthreads();
    #pragma unroll
    for (int mt = 0; mt < 2; mt++) {
        #pragma unroll
        for (int half = 0; half < 2; half++) {
            const int rl  = wm * 32 + mt * 16 + half * 8 + lr;
            const int row = bm + rl;
            float partial = 0.0f;
            #pragma unroll
            for (int nt = 0; nt < 4; nt++) {
                const int col = bn + wn * 32 + nt * 8 + lc * 2;
                float v0 = acc[mt][nt][half * 2 + 0];
                float v1 = acc[mt][nt][half * 2 + 1];
                v0 = (col     < nc) ? __expf(v0 * alpha) : 0.0f;
                v1 = (col + 1 < nc) ? __expf(v1 * alpha) : 0.0f;
                partial += v0 + v1;
                SPLIT2(v0, v1, hp, lp)
                __nv_bfloat16* dst = P2 + (size_t)z * 2 * PLP
                                    + (size_t)row * SEQ + col;
                stcs32(dst,       *reinterpret_cast<uint32_t*>(&hp));
                stcs32(dst + PLP, *reinterpret_cast<uint32_t*>(&lp));
            }
            atomicAdd(&ssum[rl], partial);
        }
    }
    __syncthreads();
    if (tid < 64) atomicAdd(rsum + z * SEQ + bm + tid, ssum[tid]);
}

// ---------------------------------------------------------------------------
// PV: out = (P2 @ Vt2) / rsum, per-batch K extent = ncp[z]. grid (4, 64, 4).
// ---------------------------------------------------------------------------
__global__ void __launch_bounds__(256, 3)
gemm_pv(const __nv_bfloat16* __restrict__ P2, const __nv_bfloat16* __restrict__ Vt2,
        float* __restrict__ out, const float* __restrict__ rsum,
        const int* __restrict__ ncp)
{
    extern __shared__ __align__(128) char smem[];
    const uint32_t sbase = smem_u32(smem);
    const int tid = threadIdx.x;
    const int z   = blockIdx.z;
    const int bm  = blockIdx.y * BM;
    const int bn  = blockIdx.x * BN;
    const int wid = tid >> 5, lane = tid & 31;
    const int wm = wid >> 2, wn = wid & 3;
    const int lr = lane >> 2, lc = lane & 3;

    LOAD_MAP()
    const __nv_bfloat16* Ab = P2  + (size_t)z * 2 * PLP;
    const __nv_bfloat16* Bb = Vt2 + (size_t)z * 2 * PLV;
    const __nv_bfloat16* aP0 = Ab + (size_t)(bm + r0) * SEQ + c0 * 8;
    const __nv_bfloat16* bP0 = Bb + (size_t)(bn + r0) * SEQ + c0 * 8;
    const __nv_bfloat16* bP1 = Bb + (size_t)(bn + r0 + 64) * SEQ + c0 * 8;
    const size_t Ap = PLP, Bp = PLV;
    const int NC = ncp[z] / BKC;

    DECL_ACC()
    GEMM_CORE()

    #pragma unroll
    for (int mt = 0; mt < 2; mt++) {
        #pragma unroll
        for (int half = 0; half < 2; half++) {
            const int row = bm + wm * 32 + mt * 16 + half * 8 + lr;
            const float inv = 1.0f / rsum[z * SEQ + row];
            #pragma unroll
            for (int nt = 0; nt < 4; nt++) {
                const int col = bn + wn * 32 + nt * 8 + lc * 2;
                stcs64f(out + (size_t)z * PLK + (size_t)row * DIM + col,
                        acc[mt][nt][half * 2 + 0] * inv,
                        acc[mt][nt][half * 2 + 1] * inv);
            }
        }
    }
}

// -------------------- mask prefix-scan (+sel build, +rs zero) ---------------
__global__ __launch_bounds__(1024)
void mask_scan_kernel(const int* __restrict__ mask, int* __restrict__ sel,
                      int* __restrict__ ncarr, int* __restrict__ ncpadarr,
                      float* __restrict__ rs)
{
    const int b   = blockIdx.x;
    const int tid = threadIdx.x;
    const int* m  = mask + b * SEQ;
    int v[4], s = 0;
    #pragma unroll
    for (int i = 0; i < 4; i++) {
        v[i] = m[tid * 4 + i];
        s += v[i];
        rs[b * SEQ + tid * 4 + i] = 0.0f;
        sel[b * SEQ + tid * 4 + i] = 0;        // padding default
    }
    const int lane = tid & 31, warp = tid >> 5;
    int sc = s;
    #pragma unroll
    for (int off = 1; off < 32; off <<= 1) {
        int t = __shfl_up_sync(0xffffffffu, sc, off);
        if (lane >= off) sc += t;
    }
    __shared__ int wsum[32];
    if (lane == 31) wsum[warp] = sc;
    __syncthreads();
    if (warp == 0) {
        int w = wsum[lane];
        #pragma unroll
        for (int off = 1; off < 32; off <<= 1) {
            int t = __shfl_up_sync(0xffffffffu, w, off);
            if (lane >= off) w += t;
        }
        wsum[lane] = w;
    }
    __syncthreads();
    int base = (warp > 0 ? wsum[warp - 1] : 0) + sc - s;   // exclusive prefix
    __syncthreads();                                       // zero-fill done
    #pragma unroll
    for (int i = 0; i < 4; i++) {
        if (v[i]) sel[b * SEQ + base] = tid * 4 + i;
        base += v[i];
    }
    if (tid == 1023) {
        ncarr[b]    = base;
        ncpadarr[b] = (base + 127) & ~127;
    }
}

// ------------ merged fp32->hi/lo split of x, Wk, Wq, Wv --------------------
#define NX (MTOT * DIM)       // 8388608
#define NWEL (DIM * DIM)      // 262144
__global__ void prep_kernel(const float* __restrict__ x,
                            const float* __restrict__ Wk,
                            const float* __restrict__ Wq,
                            const float* __restrict__ Wv,
                            __nv_bfloat16* __restrict__ x2,
                            __nv_bfloat16* __restrict__ wc2)
{
    const int i = blockIdx.x * 256 + threadIdx.x;
    float v;
    __nv_bfloat16* hi;
    if (i < NX) {
        v = x[i];
        hi = x2 + i;
        __nv_bfloat16 h = __float2bfloat16(v);
        hi[0]   = h;
        hi[PLX] = __float2bfloat16(v - __bfloat162float(h));
        return;
    }
    const int j = i - NX;
    if (j < NWEL)            { v = Wk[j];            hi = wc2 + j; }
    else if (j < 2 * NWEL)   { v = Wq[j - NWEL];     hi = wc2 + 512 * DIM + (j - NWEL); }
    else if (j < 3 * NWEL)   { v = Wv[j - 2 * NWEL]; hi = wc2 + 1024 * DIM + (j - 2 * NWEL); }
    else return;
    __nv_bfloat16 h = __float2bfloat16(v);
    hi[0]   = h;
    hi[PLW] = __float2bfloat16(v - __bfloat162float(h));
}

// zero Vt2 padding cols [nc, np) in both planes
__global__ void pad_vt_kernel(__nv_bfloat16* __restrict__ T2,
                              const int* __restrict__ ncarr,
                              const int* __restrict__ ncpadarr)
{
    const int b  = blockIdx.y;
    const int nc = ncarr[b], np = ncpadarr[b];
    const int pad = np - nc;
    if (pad == 0) return;
    const int total = pad * DIM;
    const __nv_bfloat16 zz = __float2bfloat16(0.0f);
    for (int i = blockIdx.x * blockDim.x + threadIdx.x; i < total;
         i += gridDim.x * blockDim.x) {
        const int d = i / pad;
        const int j = nc + (i - d * pad);
        __nv_bfloat16* o = T2 + (size_t)b * 2 * PLV + (size_t)d * SEQ + j;
        o[0]   = zz;
        o[PLV] = zz;
    }
}

// ---------------------------------------------------------------------------
extern "C" void kernel_launch(void* const* d_in, const int* in_sizes, int n_in,
                              void* d_out, int out_size)
{
    const float* x    = (const float*)d_in[0];
    const int*   mask = (const int*)  d_in[1];
    const float* Wk   = (const float*)d_in[2];
    const float* Wq   = (const float*)d_in[3];
    const float* Wv   = (const float*)d_in[4];
    float*       out  = (float*)d_out;

    __nv_bfloat16 *x2, *wc2, *k2, *q2c, *vt2, *p2;
    float *rs;
    int *sel, *ncv, *ncp;
    cudaGetSymbolAddress((void**)&x2,  g_x2);
    cudaGetSymbolAddress((void**)&wc2, g_Wc2);
    cudaGetSymbolAddress((void**)&k2,  g_K2);
    cudaGetSymbolAddress((void**)&q2c, g_Q2c);
    cudaGetSymbolAddress((void**)&vt2, g_Vt2);
    cudaGetSymbolAddress((void**)&p2,  g_P2);
    cudaGetSymbolAddress((void**)&rs,  g_rs);
    cudaGetSymbolAddress((void**)&sel, g_sel);
    cudaGetSymbolAddress((void**)&ncv, g_nc);
    cudaGetSymbolAddress((void**)&ncp, g_ncp);

    cudaFuncSetAttribute(gemm_qv, cudaFuncAttributeMaxDynamicSharedMemorySize, GSMEM);
    cudaFuncSetAttribute(gemm_k,  cudaFuncAttributeMaxDynamicSharedMemorySize, GSMEM);
    cudaFuncSetAttribute(gemm_s,  cudaFuncAttributeMaxDynamicSharedMemorySize, GSMEM);
    cudaFuncSetAttribute(gemm_pv, cudaFuncAttributeMaxDynamicSharedMemorySize, GSMEM);

    const float scale = 0.044194173824159216f;  // 1/sqrt(512)

    // 0) mask scan: sel + counts + rs zero
    mask_scan_kernel<<<BATCH, 1024>>>(mask, sel, ncv, ncp, rs);

    // 1) merged splits (x + [Wk;Wq;Wv])
    prep_kernel<<<(NX + 3 * NWEL + 255) / 256, 256>>>(x, Wk, Wq, Wv, x2, wc2);

    // 1b) zero Vt2 padding cols
    pad_vt_kernel<<<dim3(64, BATCH), 256>>>(vt2, ncv, ncp);

    // 2) projections
    gemm_k <<<dim3(4, 256),    256, GSMEM>>>(x2, wc2, k2);
    gemm_qv<<<dim3(8, 64, 4),  256, GSMEM>>>(x2, wc2, q2c, vt2, sel, ncv, ncp);

    // 3) scores + exp + rowsum
    gemm_s<<<dim3(32, 64, BATCH), 256, GSMEM>>>(k2, q2c, p2, rs, ncv, ncp, scale);

    // 4) out = (P2 @ Vt2) / rowsum
    gemm_pv<<<dim3(DIM / BN, SEQ / BM, BATCH), 256, GSMEM>>>(p2, vt2, out, rs, ncp);
}

// round 13
// speedup vs baseline: 1.8204x; 1.7699x over previous
#include <cuda_runtime.h>
#include <cuda_bf16.h>
#include <cuda_fp16.h>
#include <cstdint>
#include <cstddef>

#define BATCH 4
#define SEQ   4096
#define DIM   512
#define MTOT  (BATCH * SEQ)             // 16384
#define PLX   ((size_t)MTOT * DIM)      // x2 plane stride
#define PLW   ((size_t)(3 * DIM) * DIM) // Wcat2 plane stride (rows: Wk|Wq|Wv)
#define PLK   ((size_t)SEQ * DIM)       // K/Q per-batch stride (halfs)
#define PLP   ((size_t)SEQ * SEQ)       // P per-batch stride (halfs)
#define PLV   ((size_t)DIM * SEQ)       // Vt per-batch stride (halfs)

// ------------------------- scratch (device globals) -------------------------
__device__ __align__(128) __nv_bfloat16 g_x2 [2 * PLX];
__device__ __align__(128) __nv_bfloat16 g_Wc2[2 * PLW];
__device__ __align__(128) __half        g_K2h [BATCH * PLK];
__device__ __align__(128) __half        g_Q2h [BATCH * PLK];   // row-compacted
__device__ __align__(128) __half        g_Vt2h[BATCH * PLV];   // col-compacted
__device__ __align__(128) __half        g_Ph  [(size_t)BATCH * PLP];
__device__ __align__(128) float         g_rs [MTOT];
__device__ __align__(128) int           g_sel [MTOT];   // j -> t (within batch)
__device__ __align__(128) int           g_nc  [BATCH];
__device__ __align__(128) int           g_ncp [BATCH];

// ------------------------------ PTX helpers --------------------------------
__device__ __forceinline__ uint32_t smem_u32(const void* p) {
    uint32_t a;
    asm("{ .reg .u64 t; cvta.to.shared.u64 t, %1; cvt.u32.u64 %0, t; }" : "=r"(a) : "l"(p));
    return a;
}
__device__ __forceinline__ void cp16(uint32_t s, const void* g) {
    asm volatile("cp.async.cg.shared.global [%0], [%1], 16;" :: "r"(s), "l"(g));
}
__device__ __forceinline__ void cp_commit() {
    asm volatile("cp.async.commit_group;" ::: "memory");
}
template <int N>
__device__ __forceinline__ void cp_wait() {
    asm volatile("cp.async.wait_group %0;" :: "n"(N) : "memory");
}
__device__ __forceinline__ void mma16816(float* d, const uint32_t* a, const uint32_t* b) {
    asm volatile(
        "mma.sync.aligned.m16n8k16.row.col.f32.bf16.bf16.f32 "
        "{%0,%1,%2,%3}, {%4,%5,%6,%7}, {%8,%9}, {%0,%1,%2,%3};"
        : "+f"(d[0]), "+f"(d[1]), "+f"(d[2]), "+f"(d[3])
        : "r"(a[0]), "r"(a[1]), "r"(a[2]), "r"(a[3]), "r"(b[0]), "r"(b[1]));
}
__device__ __forceinline__ void mma16816h(float* d, const uint32_t* a, const uint32_t* b) {
    asm volatile(
        "mma.sync.aligned.m16n8k16.row.col.f32.f16.f16.f32 "
        "{%0,%1,%2,%3}, {%4,%5,%6,%7}, {%8,%9}, {%0,%1,%2,%3};"
        : "+f"(d[0]), "+f"(d[1]), "+f"(d[2]), "+f"(d[3])
        : "r"(a[0]), "r"(a[1]), "r"(a[2]), "r"(a[3]), "r"(b[0]), "r"(b[1]));
}
__device__ __forceinline__ void ldsm4(uint32_t* r, uint32_t addr) {
    asm volatile("ldmatrix.sync.aligned.m8n8.x4.shared.b16 {%0,%1,%2,%3}, [%4];"
                 : "=r"(r[0]), "=r"(r[1]), "=r"(r[2]), "=r"(r[3]) : "r"(addr));
}
__device__ __forceinline__ void stcs32(void* p, uint32_t v) {
    asm volatile("st.global.cs.u32 [%0], %1;" :: "l"(p), "r"(v) : "memory");
}
__device__ __forceinline__ void stcs64f(void* p, float v0, float v1) {
    asm volatile("st.global.cs.v2.f32 [%0], {%1, %2};" :: "l"(p), "f"(v0), "f"(v1) : "memory");
}
__device__ __forceinline__ uint32_t swz(int row, int chunk) {
    return (uint32_t)(row * 64 + (((chunk) ^ ((row >> 1) & 3)) << 4));
}

// ---- shared geometry ----
#define BM 64
#define BN 128
#define BKC 32

// ---- split-bf16 3-pass geometry (projections) ----
#define STAGES 3
#define TILE_A 4096
#define TILE_B 8192
#define STAGE_BYTES (2 * TILE_A + 2 * TILE_B)   // 24576
#define OFF_AL TILE_A
#define OFF_BH (2 * TILE_A)
#define OFF_BL (2 * TILE_A + TILE_B)
#define GSMEM (STAGES * STAGE_BYTES)   // 73728

// ---- fp16 single-pass geometry (scores / PV) ----
#define STAGES1 4
#define STAGE1_BYTES 12288             // A 4096 | B 8192
#define OFF1_B 4096
#define GSMEM1 (STAGES1 * STAGE1_BYTES) // 49152

// -------- split-bf16 3-pass mainloop (A=hi/lo, B=hi/lo planes) -------------
#define GEMM_CORE()                                                            \
    const int arow_l = wm * 32 + ((lane >> 3) & 1) * 8 + (lane & 7);           \
    const int akb    = lane >> 4;                                              \
    const int asw    = (arow_l >> 1) & 3;                                      \
    const uint32_t abase = (uint32_t)(arow_l * 64);                            \
    const int brow_l = wn * 32 + ((lane >> 4) & 1) * 8 + (lane & 7);           \
    const int bkb    = (lane >> 3) & 1;                                        \
    const int bsw    = (brow_l >> 1) & 3;                                      \
    const uint32_t bbase = (uint32_t)(brow_l * 64);                            \
    auto load_stage = [&](int s, int kb) {                                     \
        const uint32_t st = sbase + s * STAGE_BYTES;                           \
        const int ko = kb * BKC;                                               \
        cp16(st + soA,           aP0 + ko);                                    \
        cp16(st + OFF_AL + soA,  aP0 + Ap + ko);                               \
        cp16(st + OFF_BH + soB0, bP0 + ko);                                    \
        cp16(st + OFF_BL + soB0, bP0 + Bp + ko);                               \
        cp16(st + OFF_BH + soB1, bP1 + ko);                                    \
        cp16(st + OFF_BL + soB1, bP1 + Bp + ko);                               \
    };                                                                         \
    _Pragma("unroll")                                                          \
    for (int s = 0; s < STAGES - 1; s++) { load_stage(s, s); cp_commit(); }    \
    for (int i = 0; i < NC; i++) {                                             \
        const int pf = i + STAGES - 1;                                         \
        if (pf < NC) load_stage(pf % STAGES, pf);                              \
        cp_commit();                                                           \
        cp_wait<STAGES - 1>();                                                 \
        __syncthreads();                                                       \
        const uint32_t st  = sbase + (i % STAGES) * STAGE_BYTES;               \
        const uint32_t sAh = st;                                               \
        const uint32_t sAl = st + OFF_AL;                                      \
        const uint32_t sBh = st + OFF_BH;                                      \
        const uint32_t sBl = st + OFF_BL;                                      \
        _Pragma("unroll")                                                      \
        for (int k16 = 0; k16 < 2; k16++) {                                    \
            const uint32_t axo = (uint32_t)(((2 * k16 + akb) ^ asw) << 4);     \
            const uint32_t bxo = (uint32_t)(((2 * k16 + bkb) ^ bsw) << 4);     \
            uint32_t af[2][4], bh[4][2], bl[4][2];                             \
            _Pragma("unroll")                                                  \
            for (int mt = 0; mt < 2; mt++)                                     \
                ldsm4(af[mt], sAh + abase + mt * 1024 + axo);                  \
            _Pragma("unroll")                                                  \
            for (int ntp = 0; ntp < 2; ntp++) {                                \
                uint32_t t4[4];                                                \
                ldsm4(t4, sBh + bbase + ntp * 1024 + bxo);                     \
                bh[ntp * 2 + 0][0] = t4[0]; bh[ntp * 2 + 0][1] = t4[1];        \
                bh[ntp * 2 + 1][0] = t4[2]; bh[ntp * 2 + 1][1] = t4[3];        \
            }                                                                  \
            _Pragma("unroll")                                                  \
            for (int ntp = 0; ntp < 2; ntp++) {                                \
                uint32_t t4[4];                                                \
                ldsm4(t4, sBl + bbase + ntp * 1024 + bxo);                     \
                bl[ntp * 2 + 0][0] = t4[0]; bl[ntp * 2 + 0][1] = t4[1];        \
                bl[ntp * 2 + 1][0] = t4[2]; bl[ntp * 2 + 1][1] = t4[3];        \
            }                                                                  \
            _Pragma("unroll")                                                  \
            for (int mt = 0; mt < 2; mt++)                                     \
                _Pragma("unroll")                                              \
                for (int nt = 0; nt < 4; nt++)                                 \
                    mma16816(acc[mt][nt], af[mt], bh[nt]);                     \
            _Pragma("unroll")                                                  \
            for (int mt = 0; mt < 2; mt++)                                     \
                _Pragma("unroll")                                              \
                for (int nt = 0; nt < 4; nt++)                                 \
                    mma16816(acc[mt][nt], af[mt], bl[nt]);                     \
            _Pragma("unroll")                                                  \
            for (int mt = 0; mt < 2; mt++)                                     \
                ldsm4(af[mt], sAl + abase + mt * 1024 + axo);                  \
            _Pragma("unroll")                                                  \
            for (int mt = 0; mt < 2; mt++)                                     \
                _Pragma("unroll")                                              \
                for (int nt = 0; nt < 4; nt++)                                 \
                    mma16816(acc[mt][nt], af[mt], bh[nt]);                     \
        }                                                                      \
        __syncthreads();                                                       \
    }

// -------- fp16 single-pass mainloop (A, B single planes) -------------------
#define GEMM1_CORE()                                                           \
    const int arow_l = wm * 32 + ((lane >> 3) & 1) * 8 + (lane & 7);           \
    const int akb    = lane >> 4;                                              \
    const int asw    = (arow_l >> 1) & 3;                                      \
    const uint32_t abase = (uint32_t)(arow_l * 64);                            \
    const int brow_l = wn * 32 + ((lane >> 4) & 1) * 8 + (lane & 7);           \
    const int bkb    = (lane >> 3) & 1;                                        \
    const int bsw    = (brow_l >> 1) & 3;                                      \
    const uint32_t bbase = (uint32_t)(brow_l * 64);                            \
    auto load_stage = [&](int s, int kb) {                                     \
        const uint32_t st = sbase + s * STAGE1_BYTES;                          \
        const int ko = kb * BKC;                                               \
        cp16(st + soA,           aP0 + ko);                                    \
        cp16(st + OFF1_B + soB0, bP0 + ko);                                    \
        cp16(st + OFF1_B + soB1, bP1 + ko);                                    \
    };                                                                         \
    _Pragma("unroll")                                                          \
    for (int s = 0; s < STAGES1 - 1; s++) { load_stage(s, s); cp_commit(); }   \
    for (int i = 0; i < NC; i++) {                                             \
        const int pf = i + STAGES1 - 1;                                        \
        if (pf < NC) load_stage(pf % STAGES1, pf);                             \
        cp_commit();                                                           \
        cp_wait<STAGES1 - 1>();                                                \
        __syncthreads();                                                       \
        const uint32_t st = sbase + (i % STAGES1) * STAGE1_BYTES;              \
        _Pragma("unroll")                                                      \
        for (int k16 = 0; k16 < 2; k16++) {                                    \
            const uint32_t axo = (uint32_t)(((2 * k16 + akb) ^ asw) << 4);     \
            const uint32_t bxo = (uint32_t)(((2 * k16 + bkb) ^ bsw) << 4);     \
            uint32_t af[2][4];                                                 \
            _Pragma("unroll")                                                  \
            for (int mt = 0; mt < 2; mt++)                                     \
                ldsm4(af[mt], st + abase + mt * 1024 + axo);                   \
            _Pragma("unroll")                                                  \
            for (int ntp = 0; ntp < 2; ntp++) {                                \
                uint32_t t4[4];                                                \
                ldsm4(t4, st + OFF1_B + bbase + ntp * 1024 + bxo);             \
                uint32_t b0[2] = {t4[0], t4[1]};                               \
                uint32_t b1[2] = {t4[2], t4[3]};                               \
                _Pragma("unroll")                                              \
                for (int mt = 0; mt < 2; mt++) {                               \
                    mma16816h(acc[mt][ntp * 2 + 0], af[mt], b0);               \
                    mma16816h(acc[mt][ntp * 2 + 1], af[mt], b1);               \
                }                                                              \
            }                                                                  \
        }                                                                      \
        __syncthreads();                                                       \
    }

#define DECL_ACC()                                                             \
    float acc[2][4][4];                                                        \
    _Pragma("unroll")                                                          \
    for (int mt = 0; mt < 2; mt++)                                             \
        _Pragma("unroll")                                                      \
        for (int nt = 0; nt < 4; nt++)                                         \
            _Pragma("unroll")                                                  \
            for (int j = 0; j < 4; j++) acc[mt][nt][j] = 0.0f;

#define LOAD_MAP()                                                             \
    const int r0 = tid >> 2, c0 = tid & 3;                                     \
    const uint32_t soA  = swz(r0, c0);                                         \
    const uint32_t soB0 = soA;                                                 \
    const uint32_t soB1 = swz(r0 + 64, c0);

// ---------------------------------------------------------------------------
// QV projection (split-bf16 3-pass), compacted rows. grid (8, 64, 4).
// cols [0,512) -> Q2h (fp16); [512,1024) -> Vt2h (fp16, transposed).
// ---------------------------------------------------------------------------
__global__ void __launch_bounds__(256, 3)
gemm_qv(const __nv_bfloat16* __restrict__ x2, const __nv_bfloat16* __restrict__ Wc2,
        __half* __restrict__ Q2h, __half* __restrict__ Vt2h,
        const int* __restrict__ sel, const int* __restrict__ ncv,
        const int* __restrict__ ncp)
{
    extern __shared__ __align__(128) char smem[];
    const uint32_t sbase = smem_u32(smem);
    const int tid = threadIdx.x;
    const int z   = blockIdx.z;
    const int bm  = blockIdx.y * BM;
    if (bm >= ncp[z]) return;
    const int nc  = ncv[z];
    const int bn  = blockIdx.x * BN;
    const int wid = tid >> 5, lane = tid & 31;
    const int wm = wid >> 2, wn = wid & 3;
    const int lr = lane >> 2, lc = lane & 3;

    LOAD_MAP()
    const int t0 = sel[z * SEQ + bm + r0];
    const __nv_bfloat16* aP0 = x2 + ((size_t)z * SEQ + t0) * DIM + c0 * 8;
    const __nv_bfloat16* Wqv = Wc2 + (size_t)512 * DIM;
    const __nv_bfloat16* bP0 = Wqv + (size_t)(bn + r0) * DIM + c0 * 8;
    const __nv_bfloat16* bP1 = Wqv + (size_t)(bn + r0 + 64) * DIM + c0 * 8;
    const size_t Ap = PLX, Bp = PLW;
    const int NC = DIM / BKC;

    DECL_ACC()
    GEMM_CORE()

    if (bn < 512) {
        #pragma unroll
        for (int mt = 0; mt < 2; mt++) {
            #pragma unroll
            for (int half = 0; half < 2; half++) {
                const int j = bm + wm * 32 + mt * 16 + half * 8 + lr;
                if (j >= nc) continue;
                #pragma unroll
                for (int nt = 0; nt < 4; nt++) {
                    const int c = bn + wn * 32 + nt * 8 + lc * 2;
                    __half2 hv = __halves2half2(
                        __float2half_rn(acc[mt][nt][half * 2 + 0]),
                        __float2half_rn(acc[mt][nt][half * 2 + 1]));
                    *reinterpret_cast<__half2*>(Q2h + (size_t)z * PLK
                        + (size_t)j * DIM + c) = hv;
                }
            }
        }
    } else {
        // V epilogue: smem transpose [64 tok][128 d] -> fp16 Vt2h
        float* sv = reinterpret_cast<float*>(smem);   // [64][129]
        #pragma unroll
        for (int mt = 0; mt < 2; mt++) {
            #pragma unroll
            for (int half = 0; half < 2; half++) {
                const int tok = wm * 32 + mt * 16 + half * 8 + lr;
                #pragma unroll
                for (int nt = 0; nt < 4; nt++) {
                    const int c = wn * 32 + nt * 8 + lc * 2;
                    sv[tok * 129 + c]     = acc[mt][nt][half * 2 + 0];
                    sv[tok * 129 + c + 1] = acc[mt][nt][half * 2 + 1];
                }
            }
        }
        __syncthreads();
        const int d0 = bn - 512;
        #pragma unroll
        for (int tg = 0; tg < 2; tg++) {
            const int tok = tg * 32 + lane;
            const int j   = bm + tok;
            if (j >= nc) continue;
            __half* base = Vt2h + (size_t)z * PLV + j;
            #pragma unroll
            for (int dd = 0; dd < 16; dd++) {
                const int d = wid * 16 + dd;
                base[(size_t)(d0 + d) * SEQ] = __float2half_rn(sv[tok * 129 + d]);
            }
        }
    }
}

// ---------------------------------------------------------------------------
// K projection (split-bf16 3-pass): all tokens, N=512 -> K2h fp16. grid (4,256).
// ---------------------------------------------------------------------------
__global__ void __launch_bounds__(256, 3)
gemm_k(const __nv_bfloat16* __restrict__ x2, const __nv_bfloat16* __restrict__ Wc2,
       __half* __restrict__ K2h)
{
    extern __shared__ __align__(128) char smem[];
    const uint32_t sbase = smem_u32(smem);
    const int tid = threadIdx.x;
    const int bm  = blockIdx.y * BM;
    const int bn  = blockIdx.x * BN;
    const int wid = tid >> 5, lane = tid & 31;
    const int wm = wid >> 2, wn = wid & 3;
    const int lr = lane >> 2, lc = lane & 3;

    LOAD_MAP()
    const __nv_bfloat16* aP0 = x2 + (size_t)(bm + r0) * DIM + c0 * 8;
    const __nv_bfloat16* bP0 = Wc2 + (size_t)(bn + r0) * DIM + c0 * 8;
    const __nv_bfloat16* bP1 = Wc2 + (size_t)(bn + r0 + 64) * DIM + c0 * 8;
    const size_t Ap = PLX, Bp = PLW;
    const int NC = DIM / BKC;

    DECL_ACC()
    GEMM_CORE()

    #pragma unroll
    for (int mt = 0; mt < 2; mt++) {
        #pragma unroll
        for (int half = 0; half < 2; half++) {
            const int row = bm + wm * 32 + mt * 16 + half * 8 + lr;
            const int b = row >> 12;
            const int orow = row & 4095;
            #pragma unroll
            for (int nt = 0; nt < 4; nt++) {
                const int c = bn + wn * 32 + nt * 8 + lc * 2;
                __half2 hv = __halves2half2(
                    __float2half_rn(acc[mt][nt][half * 2 + 0]),
                    __float2half_rn(acc[mt][nt][half * 2 + 1]));
                *reinterpret_cast<__half2*>(K2h + (size_t)b * PLK
                    + (size_t)orow * DIM + c) = hv;
            }
        }
    }
}

// ---------------------------------------------------------------------------
// Scores (fp16 single-pass): Ph = exp(scale * K2h @ Q2h^T), col<nc gate,
// rowsum atomics. grid (32, 64, 4); early exit bn>=ncp[z].
// ---------------------------------------------------------------------------
__global__ void __launch_bounds__(256, 4)
gemm_s16(const __half* __restrict__ K2h, const __half* __restrict__ Q2h,
         __half* __restrict__ Ph, float* __restrict__ rsum,
         const int* __restrict__ ncv, const int* __restrict__ ncp, float alpha)
{
    extern __shared__ __align__(128) char smem[];
    const uint32_t sbase = smem_u32(smem);
    const int tid = threadIdx.x;
    const int z   = blockIdx.z;
    const int bn  = blockIdx.x * BN;
    const int bm  = blockIdx.y * BM;
    if (bn >= ncp[z]) return;
    const int nc  = ncv[z];
    const int wid = tid >> 5, lane = tid & 31;
    const int wm = wid >> 2, wn = wid & 3;
    const int lr = lane >> 2, lc = lane & 3;

    LOAD_MAP()
    const __half* Ab = K2h + (size_t)z * PLK;
    const __half* Bb = Q2h + (size_t)z * PLK;
    const __half* aP0 = Ab + (size_t)(bm + r0) * DIM + c0 * 8;
    const __half* bP0 = Bb + (size_t)(bn + r0) * DIM + c0 * 8;
    const __half* bP1 = Bb + (size_t)(bn + r0 + 64) * DIM + c0 * 8;
    const int NC = DIM / BKC;

    DECL_ACC()
    GEMM1_CORE()

    float* ssum = reinterpret_cast<float*>(smem);
    if (tid < 64) ssum[tid] = 0.0f;
    __syncthreads();
    #pragma unroll
    for (int mt = 0; mt < 2; mt++) {
        #pragma unroll
        for (int half = 0; half < 2; half++) {
            const int rl  = wm * 32 + mt * 16 + half * 8 + lr;
            const int row = bm + rl;
            float partial = 0.0f;
            #pragma unroll
            for (int nt = 0; nt < 4; nt++) {
                const int col = bn + wn * 32 + nt * 8 + lc * 2;
                float v0 = acc[mt][nt][half * 2 + 0];
                float v1 = acc[mt][nt][half * 2 + 1];
                v0 = (col     < nc) ? __expf(v0 * alpha) : 0.0f;
                v1 = (col + 1 < nc) ? __expf(v1 * alpha) : 0.0f;
                partial += v0 + v1;
                __half2 hv = __halves2half2(__float2half_rn(v0), __float2half_rn(v1));
                stcs32(Ph + (size_t)z * PLP + (size_t)row * SEQ + col,
                       *reinterpret_cast<uint32_t*>(&hv));
            }
            atomicAdd(&ssum[rl], partial);
        }
    }
    __syncthreads();
    if (tid < 64) atomicAdd(rsum + z * SEQ + bm + tid, ssum[tid]);
}

// ---------------------------------------------------------------------------
// PV (fp16 single-pass): out = (Ph @ Vt2h) / rsum, K extent = ncp[z].
// grid (4, 64, 4).
// ---------------------------------------------------------------------------
__global__ void __launch_bounds__(256, 4)
gemm_pv16(const __half* __restrict__ Ph, const __half* __restrict__ Vt2h,
          float* __restrict__ out, const float* __restrict__ rsum,
          const int* __restrict__ ncp)
{
    extern __shared__ __align__(128) char smem[];
    const uint32_t sbase = smem_u32(smem);
    const int tid = threadIdx.x;
    const int z   = blockIdx.z;
    const int bm  = blockIdx.y * BM;
    const int bn  = blockIdx.x * BN;
    const int wid = tid >> 5, lane = tid & 31;
    const int wm = wid >> 2, wn = wid & 3;
    const int lr = lane >> 2, lc = lane & 3;

    LOAD_MAP()
    const __half* Ab = Ph   + (size_t)z * PLP;
    const __half* Bb = Vt2h + (size_t)z * PLV;
    const __half* aP0 = Ab + (size_t)(bm + r0) * SEQ + c0 * 8;
    const __half* bP0 = Bb + (size_t)(bn + r0) * SEQ + c0 * 8;
    const __half* bP1 = Bb + (size_t)(bn + r0 + 64) * SEQ + c0 * 8;
    const int NC = ncp[z] / BKC;

    DECL_ACC()
    GEMM1_CORE()

    #pragma unroll
    for (int mt = 0; mt < 2; mt++) {
        #pragma unroll
        for (int half = 0; half < 2; half++) {
            const int row = bm + wm * 32 + mt * 16 + half * 8 + lr;
            const float inv = 1.0f / rsum[z * SEQ + row];
            #pragma unroll
            for (int nt = 0; nt < 4; nt++) {
                const int col = bn + wn * 32 + nt * 8 + lc * 2;
                stcs64f(out + (size_t)z * PLK + (size_t)row * DIM + col,
                        acc[mt][nt][half * 2 + 0] * inv,
                        acc[mt][nt][half * 2 + 1] * inv);
            }
        }
    }
}

// -------------------- mask prefix-scan (+sel build, +rs zero) ---------------
__global__ __launch_bounds__(1024)
void mask_scan_kernel(const int* __restrict__ mask, int* __restrict__ sel,
                      int* __restrict__ ncarr, int* __restrict__ ncpadarr,
                      float* __restrict__ rs)
{
    const int b   = blockIdx.x;
    const int tid = threadIdx.x;
    const int* m  = mask + b * SEQ;
    int v[4], s = 0;
    #pragma unroll
    for (int i = 0; i < 4; i++) {
        v[i] = m[tid * 4 + i];
        s += v[i];
        rs[b * SEQ + tid * 4 + i] = 0.0f;
        sel[b * SEQ + tid * 4 + i] = 0;
    }
    const int lane = tid & 31, warp = tid >> 5;
    int sc = s;
    #pragma unroll
    for (int off = 1; off < 32; off <<= 1) {
        int t = __shfl_up_sync(0xffffffffu, sc, off);
        if (lane >= off) sc += t;
    }
    __shared__ int wsum[32];
    if (lane == 31) wsum[warp] = sc;
    __syncthreads();
    if (warp == 0) {
        int w = wsum[lane];
        #pragma unroll
        for (int off = 1; off < 32; off <<= 1) {
            int t = __shfl_up_sync(0xffffffffu, w, off);
            if (lane >= off) w += t;
        }
        wsum[lane] = w;
    }
    __syncthreads();
    int base = (warp > 0 ? wsum[warp - 1] : 0) + sc - s;
    __syncthreads();
    #pragma unroll
    for (int i = 0; i < 4; i++) {
        if (v[i]) sel[b * SEQ + base] = tid * 4 + i;
        base += v[i];
    }
    if (tid == 1023) {
        ncarr[b]    = base;
        ncpadarr[b] = (base + 127) & ~127;
    }
}

// ------------ merged fp32->hi/lo split of x, Wk, Wq, Wv --------------------
#define NX (MTOT * DIM)
#define NWEL (DIM * DIM)
__global__ void prep_kernel(const float* __restrict__ x,
                            const float* __restrict__ Wk,
                            const float* __restrict__ Wq,
                            const float* __restrict__ Wv,
                            __nv_bfloat16* __restrict__ x2,
                            __nv_bfloat16* __restrict__ wc2)
{
    const int i = blockIdx.x * 256 + threadIdx.x;
    float v;
    __nv_bfloat16* hi;
    if (i < NX) {
        v = x[i];
        hi = x2 + i;
        __nv_bfloat16 h = __float2bfloat16(v);
        hi[0]   = h;
        hi[PLX] = __float2bfloat16(v - __bfloat162float(h));
        return;
    }
    const int j = i - NX;
    if (j < NWEL)            { v = Wk[j];            hi = wc2 + j; }
    else if (j < 2 * NWEL)   { v = Wq[j - NWEL];     hi = wc2 + 512 * DIM + (j - NWEL); }
    else if (j < 3 * NWEL)   { v = Wv[j - 2 * NWEL]; hi = wc2 + 1024 * DIM + (j - 2 * NWEL); }
    else return;
    __nv_bfloat16 h = __float2bfloat16(v);
    hi[0]   = h;
    hi[PLW] = __float2bfloat16(v - __bfloat162float(h));
}

// zero Vt2h padding cols [nc, np)
__global__ void pad_vt_kernel(__half* __restrict__ T,
                              const int* __restrict__ ncarr,
                              const int* __restrict__ ncpadarr)
{
    const int b  = blockIdx.y;
    const int nc = ncarr[b], np = ncpadarr[b];
    const int pad = np - nc;
    if (pad == 0) return;
    const int total = pad * DIM;
    const __half zz = __float2half_rn(0.0f);
    for (int i = blockIdx.x * blockDim.x + threadIdx.x; i < total;
         i += gridDim.x * blockDim.x) {
        const int d = i / pad;
        const int j = nc + (i - d * pad);
        T[(size_t)b * PLV + (size_t)d * SEQ + j] = zz;
    }
}

// ---------------------------------------------------------------------------
extern "C" void kernel_launch(void* const* d_in, const int* in_sizes, int n_in,
                              void* d_out, int out_size)
{
    const float* x    = (const float*)d_in[0];
    const int*   mask = (const int*)  d_in[1];
    const float* Wk   = (const float*)d_in[2];
    const float* Wq   = (const float*)d_in[3];
    const float* Wv   = (const float*)d_in[4];
    float*       out  = (float*)d_out;

    __nv_bfloat16 *x2, *wc2;
    __half *k2h, *q2h, *vt2h, *ph;
    float *rs;
    int *sel, *ncv, *ncp;
    cudaGetSymbolAddress((void**)&x2,   g_x2);
    cudaGetSymbolAddress((void**)&wc2,  g_Wc2);
    cudaGetSymbolAddress((void**)&k2h,  g_K2h);
    cudaGetSymbolAddress((void**)&q2h,  g_Q2h);
    cudaGetSymbolAddress((void**)&vt2h, g_Vt2h);
    cudaGetSymbolAddress((void**)&ph,   g_Ph);
    cudaGetSymbolAddress((void**)&rs,   g_rs);
    cudaGetSymbolAddress((void**)&sel,  g_sel);
    cudaGetSymbolAddress((void**)&ncv,  g_nc);
    cudaGetSymbolAddress((void**)&ncp,  g_ncp);

    cudaFuncSetAttribute(gemm_qv,   cudaFuncAttributeMaxDynamicSharedMemorySize, GSMEM);
    cudaFuncSetAttribute(gemm_k,    cudaFuncAttributeMaxDynamicSharedMemorySize, GSMEM);
    cudaFuncSetAttribute(gemm_s16,  cudaFuncAttributeMaxDynamicSharedMemorySize, GSMEM1);
    cudaFuncSetAttribute(gemm_pv16, cudaFuncAttributeMaxDynamicSharedMemorySize, GSMEM1);

    const float scale = 0.044194173824159216f;  // 1/sqrt(512)

    // 0) mask scan: sel + counts + rs zero
    mask_scan_kernel<<<BATCH, 1024>>>(mask, sel, ncv, ncp, rs);

    // 1) merged splits (x + [Wk;Wq;Wv]) -> bf16 hi/lo planes
    prep_kernel<<<(NX + 3 * NWEL + 255) / 256, 256>>>(x, Wk, Wq, Wv, x2, wc2);

    // 1b) zero Vt2h padding cols
    pad_vt_kernel<<<dim3(64, BATCH), 256>>>(vt2h, ncv, ncp);

    // 2) projections (split-bf16 compute, fp16 outputs)
    gemm_k <<<dim3(4, 256),    256, GSMEM>>>(x2, wc2, k2h);
    gemm_qv<<<dim3(8, 64, 4),  256, GSMEM>>>(x2, wc2, q2h, vt2h, sel, ncv, ncp);

    // 3) scores (fp16 single-pass) + exp + rowsum
    gemm_s16<<<dim3(32, 64, BATCH), 256, GSMEM1>>>(k2h, q2h, ph, rs, ncv, ncp, scale);

    // 4) out = (Ph @ Vt2h) / rowsum (fp16 single-pass)
    gemm_pv16<<<dim3(4, 64, BATCH), 256, GSMEM1>>>(ph, vt2h, out, rs, ncp);
}

// round 15
// speedup vs baseline: 2.2310x; 1.2256x over previous
#include <cuda_runtime.h>
#include <cuda_fp16.h>
#include <cstdint>
#include <cstddef>

#define BATCH 4
#define SEQ   4096
#define DIM   512
#define MTOT  (BATCH * SEQ)             // 16384
#define PLX   ((size_t)MTOT * DIM)      // x_h elements
#define PLW   ((size_t)(3 * DIM) * DIM) // Wc_h elements (rows: Wk|Wq|Wv)
#define PLK   ((size_t)SEQ * DIM)       // K/Q per-batch stride
#define PLP   ((size_t)SEQ * SEQ)       // P per-batch stride
#define PLV   ((size_t)DIM * SEQ)       // Vt per-batch stride

// ------------------------- scratch (device globals) -------------------------
__device__ __align__(128) __half g_xh  [PLX];
__device__ __align__(128) __half g_Wch [PLW];
__device__ __align__(128) __half g_K2h [BATCH * PLK];
__device__ __align__(128) __half g_Q2h [BATCH * PLK];   // row-compacted
__device__ __align__(128) __half g_Vt2h[BATCH * PLV];   // col-compacted
__device__ __align__(128) __half g_Ph  [(size_t)BATCH * PLP];
__device__ __align__(128) float  g_rs [MTOT];
__device__ __align__(128) int    g_sel [MTOT];          // j -> t (within batch)
__device__ __align__(128) int    g_nc  [BATCH];
__device__ __align__(128) int    g_ncp [BATCH];

// ------------------------------ PTX helpers --------------------------------
__device__ __forceinline__ uint32_t smem_u32(const void* p) {
    uint32_t a;
    asm("{ .reg .u64 t; cvta.to.shared.u64 t, %1; cvt.u32.u64 %0, t; }" : "=r"(a) : "l"(p));
    return a;
}
__device__ __forceinline__ void cp16(uint32_t s, const void* g) {
    asm volatile("cp.async.cg.shared.global [%0], [%1], 16;" :: "r"(s), "l"(g));
}
__device__ __forceinline__ void cp_commit() {
    asm volatile("cp.async.commit_group;" ::: "memory");
}
template <int N>
__device__ __forceinline__ void cp_wait() {
    asm volatile("cp.async.wait_group %0;" :: "n"(N) : "memory");
}
__device__ __forceinline__ void mma16816h(float* d, const uint32_t* a, const uint32_t* b) {
    asm volatile(
        "mma.sync.aligned.m16n8k16.row.col.f32.f16.f16.f32 "
        "{%0,%1,%2,%3}, {%4,%5,%6,%7}, {%8,%9}, {%0,%1,%2,%3};"
        : "+f"(d[0]), "+f"(d[1]), "+f"(d[2]), "+f"(d[3])
        : "r"(a[0]), "r"(a[1]), "r"(a[2]), "r"(a[3]), "r"(b[0]), "r"(b[1]));
}
__device__ __forceinline__ void ldsm4(uint32_t* r, uint32_t addr) {
    asm volatile("ldmatrix.sync.aligned.m8n8.x4.shared.b16 {%0,%1,%2,%3}, [%4];"
                 : "=r"(r[0]), "=r"(r[1]), "=r"(r[2]), "=r"(r[3]) : "r"(addr));
}
__device__ __forceinline__ void stcs32(void* p, uint32_t v) {
    asm volatile("st.global.cs.u32 [%0], %1;" :: "l"(p), "r"(v) : "memory");
}
__device__ __forceinline__ void stcs64f(void* p, float v0, float v1) {
    asm volatile("st.global.cs.v2.f32 [%0], {%1, %2};" :: "l"(p), "f"(v0), "f"(v1) : "memory");
}
__device__ __forceinline__ uint32_t swz(int row, int chunk) {
    return (uint32_t)(row * 64 + (((chunk) ^ ((row >> 1) & 3)) << 4));
}

// ---- geometry: BM=64 x BN=128, BK=32, 4 stages, 4 CTAs/SM -----------------
#define BM 64
#define BN 128
#define BKC 32
#define STAGES1 4
#define STAGE1_BYTES 12288             // A 4096 | B 8192
#define OFF1_B 4096
#define GSMEM1 (STAGES1 * STAGE1_BYTES) // 49152

// fp16 single-pass mainloop. Requires: tid, sbase, wm, wn, lane, NC, acc,
// aP0, bP0, bP1 (half* row pointers incl. +c0*8), soA, soB0, soB1.
#define GEMM1_CORE()                                                           \
    const int arow_l = wm * 32 + ((lane >> 3) & 1) * 8 + (lane & 7);           \
    const int akb    = lane >> 4;                                              \
    const int asw    = (arow_l >> 1) & 3;                                      \
    const uint32_t abase = (uint32_t)(arow_l * 64);                            \
    const int brow_l = wn * 32 + ((lane >> 4) & 1) * 8 + (lane & 7);           \
    const int bkb    = (lane >> 3) & 1;                                        \
    const int bsw    = (brow_l >> 1) & 3;                                      \
    const uint32_t bbase = (uint32_t)(brow_l * 64);                            \
    auto load_stage = [&](int s, int kb) {                                     \
        const uint32_t st = sbase + s * STAGE1_BYTES;                          \
        const int ko = kb * BKC;                                               \
        cp16(st + soA,           aP0 + ko);                                    \
        cp16(st + OFF1_B + soB0, bP0 + ko);                                    \
        cp16(st + OFF1_B + soB1, bP1 + ko);                                    \
    };                                                                         \
    _Pragma("unroll")                                                          \
    for (int s = 0; s < STAGES1 - 1; s++) { load_stage(s, s); cp_commit(); }   \
    for (int i = 0; i < NC; i++) {                                             \
        const int pf = i + STAGES1 - 1;                                        \
        if (pf < NC) load_stage(pf % STAGES1, pf);                             \
        cp_commit();                                                           \
        cp_wait<STAGES1 - 1>();                                                \
        __syncthreads();                                                       \
        const uint32_t st = sbase + (i % STAGES1) * STAGE1_BYTES;              \
        _Pragma("unroll")                                                      \
        for (int k16 = 0; k16 < 2; k16++) {                                    \
            const uint32_t axo = (uint32_t)(((2 * k16 + akb) ^ asw) << 4);     \
            const uint32_t bxo = (uint32_t)(((2 * k16 + bkb) ^ bsw) << 4);     \
            uint32_t af[2][4];                                                 \
            _Pragma("unroll")                                                  \
            for (int mt = 0; mt < 2; mt++)                                     \
                ldsm4(af[mt], st + abase + mt * 1024 + axo);                   \
            _Pragma("unroll")                                                  \
            for (int ntp = 0; ntp < 2; ntp++) {                                \
                uint32_t t4[4];                                                \
                ldsm4(t4, st + OFF1_B + bbase + ntp * 1024 + bxo);             \
                uint32_t b0[2] = {t4[0], t4[1]};                               \
                uint32_t b1[2] = {t4[2], t4[3]};                               \
                _Pragma("unroll")                                              \
                for (int mt = 0; mt < 2; mt++) {                               \
                    mma16816h(acc[mt][ntp * 2 + 0], af[mt], b0);               \
                    mma16816h(acc[mt][ntp * 2 + 1], af[mt], b1);               \
                }                                                              \
            }                                                                  \
        }                                                                      \
        __syncthreads();                                                       \
    }

#define DECL_ACC()                                                             \
    float acc[2][4][4];                                                        \
    _Pragma("unroll")                                                          \
    for (int mt = 0; mt < 2; mt++)                                             \
        _Pragma("unroll")                                                      \
        for (int nt = 0; nt < 4; nt++)                                         \
            _Pragma("unroll")                                                  \
            for (int j = 0; j < 4; j++) acc[mt][nt][j] = 0.0f;

#define LOAD_MAP()                                                             \
    const int r0 = tid >> 2, c0 = tid & 3;                                     \
    const uint32_t soA  = swz(r0, c0);                                         \
    const uint32_t soB0 = soA;                                                 \
    const uint32_t soB1 = swz(r0 + 64, c0);

// ---------------------------------------------------------------------------
// Merged projections (one launch, flattened 1-D grid of 3072 CTAs):
//   id < 1024: K projection. bn=(id&3)*128, bm=(id>>2)*64, all 16384 tokens.
//   id >= 1024: QV per batch z=(id-1024)>>9; rem=&511: bnx=rem&7, bmy=rem>>3.
//     bm=bmy*64 (early exit >= ncp[z]); bn=bnx*128.
//     cols [0,512) -> Q2h rows j; [512,1024) -> Vt2h (transposed).
// ---------------------------------------------------------------------------
__global__ void __launch_bounds__(256, 4)
gemm_proj(const __half* __restrict__ xh, const __half* __restrict__ Wch,
          __half* __restrict__ K2h, __half* __restrict__ Q2h,
          __half* __restrict__ Vt2h,
          const int* __restrict__ sel, const int* __restrict__ ncv,
          const int* __restrict__ ncp)
{
    extern __shared__ __align__(128) char smem[];
    const uint32_t sbase = smem_u32(smem);
    const int tid = threadIdx.x;
    const int id  = blockIdx.x;
    const int wid = tid >> 5, lane = tid & 31;
    const int wm = wid >> 2, wn = wid & 3;
    const int lr = lane >> 2, lc = lane & 3;

    LOAD_MAP()
    const bool isK = (id < 1024);
    int z = 0, bm, bn, nc = 0;
    const __half *aP0, *bP0, *bP1;
    if (isK) {
        bn = (id & 3) * BN;
        bm = (id >> 2) * BM;
        aP0 = xh + (size_t)(bm + r0) * DIM + c0 * 8;
        bP0 = Wch + (size_t)(bn + r0) * DIM + c0 * 8;
        bP1 = Wch + (size_t)(bn + r0 + 64) * DIM + c0 * 8;
    } else {
        const int id2 = id - 1024;
        z = id2 >> 9;
        const int rem = id2 & 511;
        bm = (rem >> 3) * BM;
        if (bm >= ncp[z]) return;
        nc = ncv[z];
        bn = (rem & 7) * BN;
        const int t0 = sel[z * SEQ + bm + r0];
        aP0 = xh + ((size_t)z * SEQ + t0) * DIM + c0 * 8;
        const __half* Wqv = Wch + (size_t)512 * DIM;
        bP0 = Wqv + (size_t)(bn + r0) * DIM + c0 * 8;
        bP1 = Wqv + (size_t)(bn + r0 + 64) * DIM + c0 * 8;
    }
    const int NC = DIM / BKC;   // 16

    DECL_ACC()
    GEMM1_CORE()

    if (isK) {
        #pragma unroll
        for (int mt = 0; mt < 2; mt++) {
            #pragma unroll
            for (int half = 0; half < 2; half++) {
                const int row = bm + wm * 32 + mt * 16 + half * 8 + lr;
                const int b = row >> 12;
                const int orow = row & 4095;
                #pragma unroll
                for (int nt = 0; nt < 4; nt++) {
                    const int c = bn + wn * 32 + nt * 8 + lc * 2;
                    __half2 hv = __halves2half2(
                        __float2half_rn(acc[mt][nt][half * 2 + 0]),
                        __float2half_rn(acc[mt][nt][half * 2 + 1]));
                    *reinterpret_cast<__half2*>(K2h + (size_t)b * PLK
                        + (size_t)orow * DIM + c) = hv;
                }
            }
        }
    } else if (bn < 512) {
        #pragma unroll
        for (int mt = 0; mt < 2; mt++) {
            #pragma unroll
            for (int half = 0; half < 2; half++) {
                const int j = bm + wm * 32 + mt * 16 + half * 8 + lr;
                if (j >= nc) continue;
                #pragma unroll
                for (int nt = 0; nt < 4; nt++) {
                    const int c = bn + wn * 32 + nt * 8 + lc * 2;
                    __half2 hv = __halves2half2(
                        __float2half_rn(acc[mt][nt][half * 2 + 0]),
                        __float2half_rn(acc[mt][nt][half * 2 + 1]));
                    *reinterpret_cast<__half2*>(Q2h + (size_t)z * PLK
                        + (size_t)j * DIM + c) = hv;
                }
            }
        }
    } else {
        // V epilogue: smem transpose [64 tok][128 d] -> fp16 Vt2h
        float* sv = reinterpret_cast<float*>(smem);   // [64][129] = 33024 B
        #pragma unroll
        for (int mt = 0; mt < 2; mt++) {
            #pragma unroll
            for (int half = 0; half < 2; half++) {
                const int tok = wm * 32 + mt * 16 + half * 8 + lr;
                #pragma unroll
                for (int nt = 0; nt < 4; nt++) {
                    const int c = wn * 32 + nt * 8 + lc * 2;
                    sv[tok * 129 + c]     = acc[mt][nt][half * 2 + 0];
                    sv[tok * 129 + c + 1] = acc[mt][nt][half * 2 + 1];
                }
            }
        }
        __syncthreads();
        const int d0 = bn - 512;
        #pragma unroll
        for (int tg = 0; tg < 2; tg++) {
            const int tok = tg * 32 + lane;
            const int j   = bm + tok;
            if (j >= nc) continue;
            __half* base = Vt2h + (size_t)z * PLV + j;
            #pragma unroll
            for (int dd = 0; dd < 16; dd++) {
                const int d = wid * 16 + dd;
                base[(size_t)(d0 + d) * SEQ] = __float2half_rn(sv[tok * 129 + d]);
            }
        }
    }
}

// ---------------------------------------------------------------------------
// Scores: Ph = exp(scale * K2h @ Q2h^T), col<nc gate, rowsum atomics.
// grid (32, 64, 4); early exit bn>=ncp[z]. Streaming stores.
// ---------------------------------------------------------------------------
__global__ void __launch_bounds__(256, 4)
gemm_s16(const __half* __restrict__ K2h, const __half* __restrict__ Q2h,
         __half* __restrict__ Ph, float* __restrict__ rsum,
         const int* __restrict__ ncv, const int* __restrict__ ncp, float alpha)
{
    extern __shared__ __align__(128) char smem[];
    const uint32_t sbase = smem_u32(smem);
    const int tid = threadIdx.x;
    const int z   = blockIdx.z;
    const int bn  = blockIdx.x * BN;
    const int bm  = blockIdx.y * BM;
    if (bn >= ncp[z]) return;
    const int nc  = ncv[z];
    const int wid = tid >> 5, lane = tid & 31;
    const int wm = wid >> 2, wn = wid & 3;
    const int lr = lane >> 2, lc = lane & 3;

    LOAD_MAP()
    const __half* Ab = K2h + (size_t)z * PLK;
    const __half* Bb = Q2h + (size_t)z * PLK;
    const __half* aP0 = Ab + (size_t)(bm + r0) * DIM + c0 * 8;
    const __half* bP0 = Bb + (size_t)(bn + r0) * DIM + c0 * 8;
    const __half* bP1 = Bb + (size_t)(bn + r0 + 64) * DIM + c0 * 8;
    const int NC = DIM / BKC;

    DECL_ACC()
    GEMM1_CORE()

    float* ssum = reinterpret_cast<float*>(smem);
    if (tid < 64) ssum[tid] = 0.0f;
    __syncthreads();
    #pragma unroll
    for (int mt = 0; mt < 2; mt++) {
        #pragma unroll
        for (int half = 0; half < 2; half++) {
            const int rl  = wm * 32 + mt * 16 + half * 8 + lr;
            const int row = bm + rl;
            float partial = 0.0f;
            #pragma unroll
            for (int nt = 0; nt < 4; nt++) {
                const int col = bn + wn * 32 + nt * 8 + lc * 2;
                float v0 = acc[mt][nt][half * 2 + 0];
                float v1 = acc[mt][nt][half * 2 + 1];
                v0 = (col     < nc) ? __expf(v0 * alpha) : 0.0f;
                v1 = (col + 1 < nc) ? __expf(v1 * alpha) : 0.0f;
                partial += v0 + v1;
                __half2 hv = __halves2half2(__float2half_rn(v0), __float2half_rn(v1));
                stcs32(Ph + (size_t)z * PLP + (size_t)row * SEQ + col,
                       *reinterpret_cast<uint32_t*>(&hv));
            }
            atomicAdd(&ssum[rl], partial);
        }
    }
    __syncthreads();
    if (tid < 64) atomicAdd(rsum + z * SEQ + bm + tid, ssum[tid]);
}

// ---------------------------------------------------------------------------
// PV: out = (Ph @ Vt2h) / rsum, K extent = ncp[z]. grid (4, 64, 4).
// ---------------------------------------------------------------------------
__global__ void __launch_bounds__(256, 4)
gemm_pv16(const __half* __restrict__ Ph, const __half* __restrict__ Vt2h,
          float* __restrict__ out, const float* __restrict__ rsum,
          const int* __restrict__ ncp)
{
    extern __shared__ __align__(128) char smem[];
    const uint32_t sbase = smem_u32(smem);
    const int tid = threadIdx.x;
    const int z   = blockIdx.z;
    const int bm  = blockIdx.y * BM;
    const int bn  = blockIdx.x * BN;
    const int wid = tid >> 5, lane = tid & 31;
    const int wm = wid >> 2, wn = wid & 3;
    const int lr = lane >> 2, lc = lane & 3;

    LOAD_MAP()
    const __half* Ab = Ph   + (size_t)z * PLP;
    const __half* Bb = Vt2h + (size_t)z * PLV;
    const __half* aP0 = Ab + (size_t)(bm + r0) * SEQ + c0 * 8;
    const __half* bP0 = Bb + (size_t)(bn + r0) * SEQ + c0 * 8;
    const __half* bP1 = Bb + (size_t)(bn + r0 + 64) * SEQ + c0 * 8;
    const int NC = ncp[z] / BKC;

    DECL_ACC()
    GEMM1_CORE()

    #pragma unroll
    for (int mt = 0; mt < 2; mt++) {
        #pragma unroll
        for (int half = 0; half < 2; half++) {
            const int row = bm + wm * 32 + mt * 16 + half * 8 + lr;
            const float inv = 1.0f / rsum[z * SEQ + row];
            #pragma unroll
            for (int nt = 0; nt < 4; nt++) {
                const int col = bn + wn * 32 + nt * 8 + lc * 2;
                stcs64f(out + (size_t)z * PLK + (size_t)row * DIM + col,
                        acc[mt][nt][half * 2 + 0] * inv,
                        acc[mt][nt][half * 2 + 1] * inv);
            }
        }
    }
}

// -------------------- mask prefix-scan (+sel build, +rs zero) ---------------
__global__ __launch_bounds__(1024)
void mask_scan_kernel(const int* __restrict__ mask, int* __restrict__ sel,
                      int* __restrict__ ncarr, int* __restrict__ ncpadarr,
                      float* __restrict__ rs)
{
    const int b   = blockIdx.x;
    const int tid = threadIdx.x;
    const int* m  = mask + b * SEQ;
    int v[4], s = 0;
    #pragma unroll
    for (int i = 0; i < 4; i++) {
        v[i] = m[tid * 4 + i];
        s += v[i];
        rs[b * SEQ + tid * 4 + i] = 0.0f;
        sel[b * SEQ + tid * 4 + i] = 0;
    }
    const int lane = tid & 31, warp = tid >> 5;
    int sc = s;
    #pragma unroll
    for (int off = 1; off < 32; off <<= 1) {
        int t = __shfl_up_sync(0xffffffffu, sc, off);
        if (lane >= off) sc += t;
    }
    __shared__ int wsum[32];
    if (lane == 31) wsum[warp] = sc;
    __syncthreads();
    if (warp == 0) {
        int w = wsum[lane];
        #pragma unroll
        for (int off = 1; off < 32; off <<= 1) {
            int t = __shfl_up_sync(0xffffffffu, w, off);
            if (lane >= off) w += t;
        }
        wsum[lane] = w;
    }
    __syncthreads();
    int base = (warp > 0 ? wsum[warp - 1] : 0) + sc - s;
    __syncthreads();
    #pragma unroll
    for (int i = 0; i < 4; i++) {
        if (v[i]) sel[b * SEQ + base] = tid * 4 + i;
        base += v[i];
    }
    if (tid == 1023) {
        ncarr[b]    = base;
        ncpadarr[b] = (base + 127) & ~127;
    }
}

// ------------ merged fp32->fp16 conversion of x, Wk, Wq, Wv ----------------
#define NX (MTOT * DIM)
#define NWEL (DIM * DIM)
__global__ void prep_kernel(const float* __restrict__ x,
                            const float* __restrict__ Wk,
                            const float* __restrict__ Wq,
                            const float* __restrict__ Wv,
                            __half* __restrict__ xh,
                            __half* __restrict__ wch)
{
    const int i = blockIdx.x * 256 + threadIdx.x;
    if (i < NX) {
        xh[i] = __float2half_rn(x[i]);
        return;
    }
    const int j = i - NX;
    if (j < NWEL)           wch[j]                          = __float2half_rn(Wk[j]);
    else if (j < 2 * NWEL)  wch[512 * DIM + j - NWEL]       = __float2half_rn(Wq[j - NWEL]);
    else if (j < 3 * NWEL)  wch[1024 * DIM + j - 2 * NWEL]  = __float2half_rn(Wv[j - 2 * NWEL]);
}

// zero Vt2h padding cols [nc, np)
__global__ void pad_vt_kernel(__half* __restrict__ T,
                              const int* __restrict__ ncarr,
                              const int* __restrict__ ncpadarr)
{
    const int b  = blockIdx.y;
    const int nc = ncarr[b], np = ncpadarr[b];
    const int pad = np - nc;
    if (pad == 0) return;
    const int total = pad * DIM;
    const __half zz = __float2half_rn(0.0f);
    for (int i = blockIdx.x * blockDim.x + threadIdx.x; i < total;
         i += gridDim.x * blockDim.x) {
        const int d = i / pad;
        const int j = nc + (i - d * pad);
        T[(size_t)b * PLV + (size_t)d * SEQ + j] = zz;
    }
}

// ---------------------------------------------------------------------------
extern "C" void kernel_launch(void* const* d_in, const int* in_sizes, int n_in,
                              void* d_out, int out_size)
{
    const float* x    = (const float*)d_in[0];
    const int*   mask = (const int*)  d_in[1];
    const float* Wk   = (const float*)d_in[2];
    const float* Wq   = (const float*)d_in[3];
    const float* Wv   = (const float*)d_in[4];
    float*       out  = (float*)d_out;

    __half *xh, *wch, *k2h, *q2h, *vt2h, *ph;
    float *rs;
    int *sel, *ncv, *ncp;
    cudaGetSymbolAddress((void**)&xh,   g_xh);
    cudaGetSymbolAddress((void**)&wch,  g_Wch);
    cudaGetSymbolAddress((void**)&k2h,  g_K2h);
    cudaGetSymbolAddress((void**)&q2h,  g_Q2h);
    cudaGetSymbolAddress((void**)&vt2h, g_Vt2h);
    cudaGetSymbolAddress((void**)&ph,   g_Ph);
    cudaGetSymbolAddress((void**)&rs,   g_rs);
    cudaGetSymbolAddress((void**)&sel,  g_sel);
    cudaGetSymbolAddress((void**)&ncv,  g_nc);
    cudaGetSymbolAddress((void**)&ncp,  g_ncp);

    cudaFuncSetAttribute(gemm_proj, cudaFuncAttributeMaxDynamicSharedMemorySize, GSMEM1);
    cudaFuncSetAttribute(gemm_s16,  cudaFuncAttributeMaxDynamicSharedMemorySize, GSMEM1);
    cudaFuncSetAttribute(gemm_pv16, cudaFuncAttributeMaxDynamicSharedMemorySize, GSMEM1);

    const float scale = 0.044194173824159216f;  // 1/sqrt(512)

    // 0) mask scan: sel + counts + rs zero
    mask_scan_kernel<<<BATCH, 1024>>>(mask, sel, ncv, ncp, rs);

    // 1) fp32 -> fp16 conversion (x + [Wk;Wq;Wv])
    prep_kernel<<<(NX + 3 * NWEL + 255) / 256, 256>>>(x, Wk, Wq, Wv, xh, wch);

    // 1b) zero Vt2h padding cols
    pad_vt_kernel<<<dim3(64, BATCH), 256>>>(vt2h, ncv, ncp);

    // 2) merged projections (K + compacted Q/V) in ONE launch
    gemm_proj<<<3072, 256, GSMEM1>>>(xh, wch, k2h, q2h, vt2h, sel, ncv, ncp);

    // 3) scores + exp + rowsum
    gemm_s16<<<dim3(32, 64, BATCH), 256, GSMEM1>>>(k2h, q2h, ph, rs, ncv, ncp, scale);

    // 4) out = (Ph @ Vt2h) / rowsum
    gemm_pv16<<<dim3(4, 64, BATCH), 256, GSMEM1>>>(ph, vt2h, out, rs, ncp);
}